// round 1
// baseline (speedup 1.0000x reference)
#include <cuda_runtime.h>
#include <math.h>

#define D_MODEL 1024
#define SEQ     2048
#define NHEAD   16
#define DK      64
#define DFF     4096
#define NLAYERS 4

// ---------------- scratch (static device globals; no allocation) ------------
__device__ float g_x  [SEQ * D_MODEL];
__device__ float g_q  [SEQ * D_MODEL];
__device__ float g_k  [SEQ * D_MODEL];
__device__ float g_v  [SEQ * D_MODEL];
__device__ float g_ctx[SEQ * D_MODEL];
__device__ float g_t1 [SEQ * D_MODEL];
__device__ float g_h  [SEQ * DFF];
__device__ float g_att[(size_t)NHEAD * SEQ * SEQ];   // 256 MiB

// ---------------- helpers ---------------------------------------------------
__device__ __forceinline__ float gelu_f(float x) {
    // tanh approximation (jax.nn.gelu default approximate=True)
    const float c = 0.7978845608028654f;
    float t = tanhf(c * (x + 0.044715f * x * x * x));
    return 0.5f * x * (1.0f + t);
}

// ---------------- generic register-blocked SGEMM ----------------------------
// C[M,N] = alpha * A @ op(B) + bias ; op(B)=B (NN) or B^T (NT where B is [N,K])
// Batched via blockIdx.z with element strides. All dims must divide tiles.
template <int BM, int BN, int BK, int TM, int TN, int ACT, bool TRANSB>
__global__ __launch_bounds__((BM / TM) * (BN / TN))
void gemm_kernel(const float* __restrict__ A, int lda, long long batchA,
                 const float* __restrict__ B, int ldb, long long batchB,
                 float* __restrict__ C, int ldc, long long batchC,
                 const float* __restrict__ bias, int K, float alpha)
{
    constexpr int THREADS = (BM / TM) * (BN / TN);
    __shared__ float As[BK][BM + 4];
    __shared__ float Bs[BK][BN + 4];

    A += (long long)blockIdx.z * batchA;
    B += (long long)blockIdx.z * batchB;
    C += (long long)blockIdx.z * batchC;

    const int tid = threadIdx.x;
    const int bm = blockIdx.y * BM;
    const int bn = blockIdx.x * BN;
    const int tx = tid % (BN / TN);
    const int ty = tid / (BN / TN);

    float acc[TM][TN];
#pragma unroll
    for (int i = 0; i < TM; i++)
#pragma unroll
        for (int j = 0; j < TN; j++) acc[i][j] = 0.0f;

    // A-tile loader mapping (rows BM, K-contig float4)
    constexpr int BKv = BK / 4;
    const int aRow = tid / BKv;
    const int aCol = tid % BKv;
    constexpr int aStep = THREADS / BKv;
    // B-tile NN loader mapping (rows BK, N-contig float4)
    constexpr int BNv = BN / 4;
    const int bRow = tid / BNv;
    const int bCol = tid % BNv;
    constexpr int bStep = THREADS / BNv;

    for (int k0 = 0; k0 < K; k0 += BK) {
#pragma unroll
        for (int r = 0; r < BM; r += aStep) {
            float4 a4 = *(const float4*)&A[(size_t)(bm + aRow + r) * lda + k0 + aCol * 4];
            As[aCol * 4 + 0][aRow + r] = a4.x;
            As[aCol * 4 + 1][aRow + r] = a4.y;
            As[aCol * 4 + 2][aRow + r] = a4.z;
            As[aCol * 4 + 3][aRow + r] = a4.w;
        }
        if (TRANSB) {
            // B is [N, K] row-major; tile rows = BN, K-contig
#pragma unroll
            for (int r = 0; r < BN; r += aStep) {
                float4 b4 = *(const float4*)&B[(size_t)(bn + aRow + r) * ldb + k0 + aCol * 4];
                Bs[aCol * 4 + 0][aRow + r] = b4.x;
                Bs[aCol * 4 + 1][aRow + r] = b4.y;
                Bs[aCol * 4 + 2][aRow + r] = b4.z;
                Bs[aCol * 4 + 3][aRow + r] = b4.w;
            }
        } else {
#pragma unroll
            for (int r = 0; r < BK; r += bStep) {
                *(float4*)&Bs[bRow + r][bCol * 4] =
                    *(const float4*)&B[(size_t)(k0 + bRow + r) * ldb + bn + bCol * 4];
            }
        }
        __syncthreads();

#pragma unroll
        for (int kk = 0; kk < BK; kk++) {
            float ra[TM], rb[TN];
#pragma unroll
            for (int i = 0; i < TM; i += 4) {
                float4 t = *(const float4*)&As[kk][ty * TM + i];
                ra[i] = t.x; ra[i + 1] = t.y; ra[i + 2] = t.z; ra[i + 3] = t.w;
            }
#pragma unroll
            for (int j = 0; j < TN; j += 4) {
                float4 t = *(const float4*)&Bs[kk][tx * TN + j];
                rb[j] = t.x; rb[j + 1] = t.y; rb[j + 2] = t.z; rb[j + 3] = t.w;
            }
#pragma unroll
            for (int i = 0; i < TM; i++)
#pragma unroll
                for (int j = 0; j < TN; j++)
                    acc[i][j] = fmaf(ra[i], rb[j], acc[i][j]);
        }
        __syncthreads();
    }

#pragma unroll
    for (int i = 0; i < TM; i++) {
        const int row = bm + ty * TM + i;
#pragma unroll
        for (int j = 0; j < TN; j++) {
            const int col = bn + tx * TN + j;
            float vv = acc[i][j] * alpha;
            if (bias) vv += bias[col];
            if (ACT == 1) vv = gelu_f(vv);
            C[(size_t)row * ldc + col] = vv;
        }
    }
}

// ---------------- softmax over rows of length SEQ ---------------------------
__global__ __launch_bounds__(256) void softmax_kernel(float* __restrict__ att)
{
    __shared__ float red[8];
    float* row = att + (size_t)blockIdx.x * SEQ;
    const int tid = threadIdx.x;
    const int lane = tid & 31, wid = tid >> 5;

    float4 a = ((const float4*)row)[tid * 2];
    float4 b = ((const float4*)row)[tid * 2 + 1];

    float m = fmaxf(fmaxf(fmaxf(a.x, a.y), fmaxf(a.z, a.w)),
                    fmaxf(fmaxf(b.x, b.y), fmaxf(b.z, b.w)));
#pragma unroll
    for (int o = 16; o > 0; o >>= 1) m = fmaxf(m, __shfl_xor_sync(0xffffffffu, m, o));
    if (lane == 0) red[wid] = m;
    __syncthreads();
    float bmax = red[0];
#pragma unroll
    for (int i = 1; i < 8; i++) bmax = fmaxf(bmax, red[i]);
    __syncthreads();

    a.x = __expf(a.x - bmax); a.y = __expf(a.y - bmax);
    a.z = __expf(a.z - bmax); a.w = __expf(a.w - bmax);
    b.x = __expf(b.x - bmax); b.y = __expf(b.y - bmax);
    b.z = __expf(b.z - bmax); b.w = __expf(b.w - bmax);

    float s = a.x + a.y + a.z + a.w + b.x + b.y + b.z + b.w;
#pragma unroll
    for (int o = 16; o > 0; o >>= 1) s += __shfl_xor_sync(0xffffffffu, s, o);
    if (lane == 0) red[wid] = s;
    __syncthreads();
    float total = 0.0f;
#pragma unroll
    for (int i = 0; i < 8; i++) total += red[i];
    const float inv = 1.0f / total;

    a.x *= inv; a.y *= inv; a.z *= inv; a.w *= inv;
    b.x *= inv; b.y *= inv; b.z *= inv; b.w *= inv;
    ((float4*)row)[tid * 2]     = a;
    ((float4*)row)[tid * 2 + 1] = b;
}

// ---------------- fused residual add + LayerNorm (in place on x) ------------
__global__ __launch_bounds__(256) void add_ln_kernel(
    float* __restrict__ x, const float* __restrict__ res,
    const float* __restrict__ g, const float* __restrict__ b)
{
    __shared__ float red[8];
    const size_t base = (size_t)blockIdx.x * D_MODEL;
    const int tid = threadIdx.x;
    const int lane = tid & 31, wid = tid >> 5;

    float4 xv = *(const float4*)&x[base + tid * 4];
    float4 rv = *(const float4*)&res[base + tid * 4];
    float v0 = xv.x + rv.x, v1 = xv.y + rv.y, v2 = xv.z + rv.z, v3 = xv.w + rv.w;

    float s = v0 + v1 + v2 + v3;
#pragma unroll
    for (int o = 16; o > 0; o >>= 1) s += __shfl_xor_sync(0xffffffffu, s, o);
    if (lane == 0) red[wid] = s;
    __syncthreads();
    float tot = 0.0f;
#pragma unroll
    for (int i = 0; i < 8; i++) tot += red[i];
    const float mu = tot * (1.0f / D_MODEL);
    __syncthreads();

    float d0 = v0 - mu, d1 = v1 - mu, d2 = v2 - mu, d3 = v3 - mu;
    float s2 = d0 * d0 + d1 * d1 + d2 * d2 + d3 * d3;
#pragma unroll
    for (int o = 16; o > 0; o >>= 1) s2 += __shfl_xor_sync(0xffffffffu, s2, o);
    if (lane == 0) red[wid] = s2;
    __syncthreads();
    float tot2 = 0.0f;
#pragma unroll
    for (int i = 0; i < 8; i++) tot2 += red[i];
    const float rs = rsqrtf(tot2 * (1.0f / D_MODEL) + 1e-5f);

    const int c = tid * 4;
    float4 gg = *(const float4*)&g[c];
    float4 bb = *(const float4*)&b[c];
    float4 out;
    out.x = d0 * rs * gg.x + bb.x;
    out.y = d1 * rs * gg.y + bb.y;
    out.z = d2 * rs * gg.z + bb.z;
    out.w = d3 * rs * gg.w + bb.w;
    *(float4*)&x[base + c] = out;
}

// ---------------- host ------------------------------------------------------
extern "C" void kernel_launch(void* const* d_in, const int* in_sizes, int n_in,
                              void* d_out, int out_size)
{
    const float* x_in = (const float*)d_in[0];
    const float* wq = (const float*)d_in[1];
    const float* bq = (const float*)d_in[2];
    const float* wk = (const float*)d_in[3];
    const float* bk = (const float*)d_in[4];
    const float* wv = (const float*)d_in[5];
    const float* bv = (const float*)d_in[6];
    const float* wo = (const float*)d_in[7];
    const float* bo = (const float*)d_in[8];
    const float* w1 = (const float*)d_in[9];
    const float* b1 = (const float*)d_in[10];
    const float* w2 = (const float*)d_in[11];
    const float* b2 = (const float*)d_in[12];
    const float* ln1g = (const float*)d_in[13];
    const float* ln1b = (const float*)d_in[14];
    const float* ln2g = (const float*)d_in[15];
    const float* ln2b = (const float*)d_in[16];

    float *x, *q, *k, *v, *ctx, *t1, *h, *att;
    cudaGetSymbolAddress((void**)&x,   g_x);
    cudaGetSymbolAddress((void**)&q,   g_q);
    cudaGetSymbolAddress((void**)&k,   g_k);
    cudaGetSymbolAddress((void**)&v,   g_v);
    cudaGetSymbolAddress((void**)&ctx, g_ctx);
    cudaGetSymbolAddress((void**)&t1,  g_t1);
    cudaGetSymbolAddress((void**)&h,   g_h);
    cudaGetSymbolAddress((void**)&att, g_att);

    cudaMemcpyAsync(x, x_in, sizeof(float) * SEQ * D_MODEL,
                    cudaMemcpyDeviceToDevice, 0);

    const dim3 blk(256);
    const dim3 grid_dd(D_MODEL / 128, SEQ / 128, 1);      // M=2048, N=1024
    const dim3 grid_ff(DFF / 128, SEQ / 128, 1);          // M=2048, N=4096
    const dim3 grid_sc(SEQ / 128, SEQ / 128, NHEAD);      // scores
    const dim3 grid_cx(1, SEQ / 128, NHEAD);              // ctx (N=64)

    for (int l = 0; l < NLAYERS; l++) {
        const float* Wq = wq + (size_t)l * D_MODEL * D_MODEL;
        const float* Wk = wk + (size_t)l * D_MODEL * D_MODEL;
        const float* Wv = wv + (size_t)l * D_MODEL * D_MODEL;
        const float* Wo = wo + (size_t)l * D_MODEL * D_MODEL;
        const float* W1 = w1 + (size_t)l * D_MODEL * DFF;
        const float* W2 = w2 + (size_t)l * DFF * D_MODEL;

        // QKV projections
        gemm_kernel<128, 128, 16, 8, 8, 0, false><<<grid_dd, blk>>>(
            x, D_MODEL, 0, Wq, D_MODEL, 0, q, D_MODEL, 0,
            bq + (size_t)l * D_MODEL, D_MODEL, 1.0f);
        gemm_kernel<128, 128, 16, 8, 8, 0, false><<<grid_dd, blk>>>(
            x, D_MODEL, 0, Wk, D_MODEL, 0, k, D_MODEL, 0,
            bk + (size_t)l * D_MODEL, D_MODEL, 1.0f);
        gemm_kernel<128, 128, 16, 8, 8, 0, false><<<grid_dd, blk>>>(
            x, D_MODEL, 0, Wv, D_MODEL, 0, v, D_MODEL, 0,
            bv + (size_t)l * D_MODEL, D_MODEL, 1.0f);

        // scores[h] = q_h @ k_h^T / 8   (batched NT, K=64)
        gemm_kernel<128, 128, 16, 8, 8, 0, true><<<grid_sc, blk>>>(
            q, D_MODEL, DK, k, D_MODEL, DK,
            att, SEQ, (long long)SEQ * SEQ, nullptr, DK, 0.125f);

        softmax_kernel<<<NHEAD * SEQ, blk>>>(att);

        // ctx_h = attn_h @ v_h   (batched NN, M=2048, N=64, K=2048)
        gemm_kernel<128, 64, 16, 8, 4, 0, false><<<grid_cx, blk>>>(
            att, SEQ, (long long)SEQ * SEQ, v, D_MODEL, DK,
            ctx, D_MODEL, DK, nullptr, SEQ, 1.0f);

        // output projection
        gemm_kernel<128, 128, 16, 8, 8, 0, false><<<grid_dd, blk>>>(
            ctx, D_MODEL, 0, Wo, D_MODEL, 0, t1, D_MODEL, 0,
            bo + (size_t)l * D_MODEL, D_MODEL, 1.0f);

        add_ln_kernel<<<SEQ, blk>>>(x, t1,
            ln1g + (size_t)l * D_MODEL, ln1b + (size_t)l * D_MODEL);

        // FFN
        gemm_kernel<128, 128, 16, 8, 8, 1, false><<<grid_ff, blk>>>(
            x, D_MODEL, 0, W1, DFF, 0, h, DFF, 0,
            b1 + (size_t)l * DFF, D_MODEL, 1.0f);
        gemm_kernel<128, 128, 16, 8, 8, 0, false><<<grid_dd, blk>>>(
            h, DFF, 0, W2, D_MODEL, 0, t1, D_MODEL, 0,
            b2 + (size_t)l * D_MODEL, DFF, 1.0f);

        add_ln_kernel<<<SEQ, blk>>>(x, t1,
            ln2g + (size_t)l * D_MODEL, ln2b + (size_t)l * D_MODEL);
    }

    cudaMemcpyAsync(d_out, x, sizeof(float) * SEQ * D_MODEL,
                    cudaMemcpyDeviceToDevice, 0);
}

// round 4
// speedup vs baseline: 1.5538x; 1.5538x over previous
#include <cuda_runtime.h>
#include <cuda_bf16.h>
#include <math.h>
#include <stdint.h>

#define D_MODEL 1024
#define SEQ     2048
#define NHEAD   16
#define DK      64
#define DFF     4096
#define NLAYERS 4

// ===================== scratch (static device globals) ======================
__device__ float g_x  [SEQ * D_MODEL];
__device__ float g_q  [SEQ * D_MODEL];
__device__ float g_k  [SEQ * D_MODEL];
__device__ float g_v  [SEQ * D_MODEL];
__device__ float g_ctx[SEQ * D_MODEL];
__device__ float g_t1 [SEQ * D_MODEL];
__device__ float g_h  [SEQ * DFF];
__device__ float g_att[(size_t)NHEAD * SEQ * SEQ];                 // 256 MiB

// packed split-bf16 operands
// "act" layout: [hi(K) | lo(K) | hi(K)]   (A-side)
// "wgt" layout: [hi(K) | hi(K) | lo(K)]   (B-side)
__device__ __nv_bfloat16 g_xp [(size_t)SEQ * 3 * D_MODEL];
__device__ __nv_bfloat16 g_qp [(size_t)SEQ * 3 * D_MODEL];
__device__ __nv_bfloat16 g_kp [(size_t)SEQ * 3 * D_MODEL];
__device__ __nv_bfloat16 g_hp [(size_t)SEQ * 3 * DFF];
__device__ __nv_bfloat16 g_pp [(size_t)NHEAD * SEQ * 3 * SEQ];    // 402 MiB
__device__ __nv_bfloat16 g_vtp[(size_t)NHEAD * DK * 3 * SEQ];
__device__ __nv_bfloat16 g_wqp[(size_t)D_MODEL * 3 * D_MODEL];
__device__ __nv_bfloat16 g_wkp[(size_t)D_MODEL * 3 * D_MODEL];
__device__ __nv_bfloat16 g_wvp[(size_t)D_MODEL * 3 * D_MODEL];
__device__ __nv_bfloat16 g_wop[(size_t)D_MODEL * 3 * D_MODEL];
__device__ __nv_bfloat16 g_w1p[(size_t)DFF * 3 * D_MODEL];
__device__ __nv_bfloat16 g_w2p[(size_t)D_MODEL * 3 * DFF];

// ===================== helpers =============================================
__device__ __forceinline__ uint32_t smem_to_u32(const void* p) {
    uint32_t a;
    asm("{ .reg .u64 t; cvta.to.shared.u64 t, %1; cvt.u32.u64 %0, t; }"
        : "=r"(a) : "l"(p));
    return a;
}

__device__ __forceinline__ float gelu_f(float x) {
    const float c = 0.7978845608028654f;
    float t = tanhf(c * (x + 0.044715f * x * x * x));
    return 0.5f * x * (1.0f + t);
}

#define CP_ASYNC16(dst, src) \
    asm volatile("cp.async.cg.shared.global [%0], [%1], 16;" \
        :: "r"(dst), "l"(src) : "memory")
#define CP_COMMIT() asm volatile("cp.async.commit_group;" ::: "memory")
#define CP_WAIT(N)  asm volatile("cp.async.wait_group %0;" :: "n"(N) : "memory")

#define LDMATRIX_X4(r0, r1, r2, r3, addr) \
    asm volatile("ldmatrix.sync.aligned.m8n8.x4.shared.b16 {%0,%1,%2,%3}, [%4];" \
        : "=r"(r0), "=r"(r1), "=r"(r2), "=r"(r3) : "r"(addr))

#define MMA_16816(c, a, b0, b1) \
    asm volatile("mma.sync.aligned.m16n8k16.row.col.f32.bf16.bf16.f32 " \
        "{%0,%1,%2,%3}, {%4,%5,%6,%7}, {%8,%9}, {%0,%1,%2,%3};" \
        : "+f"((c)[0]), "+f"((c)[1]), "+f"((c)[2]), "+f"((c)[3]) \
        : "r"((a)[0]), "r"((a)[1]), "r"((a)[2]), "r"((a)[3]), \
          "r"(b0), "r"(b1))

// ===================== HMMA split-bf16 GEMM =================================
// C[128, BN] tile = alpha * sum_k A'[m,k] * B'[n,k]  (+bias, +GELU)
// A' [M,lda], B' [N,ldb] both row-major bf16, K-contiguous (NT gemm).
// K swept in 32-elem chunks over 3 segments: seg s covers
// [s*segStride, s*segStride + segIters*32).
#define SA 80   // padded smem row stride bytes (40 bf16) -> LDSM conflict-free

template <int BN, int ACT>
__global__ __launch_bounds__(256)
void gemm_tc(const __nv_bfloat16* __restrict__ A, int lda, long long batchA,
             const __nv_bfloat16* __restrict__ B, int ldb, long long batchB,
             float* __restrict__ C, int ldc, long long batchC,
             const float* __restrict__ bias, int segIters, int segStride,
             float alpha)
{
    constexpr int WN    = BN / 2;      // warp n-tile (warps laid out 4m x 2n)
    constexpr int NG    = WN / 16;     // ldmatrix.x4 groups per warp (n16 each)
    constexpr int ATILE = 128 * SA;
    constexpr int BTILE = BN * SA;
    __shared__ __align__(16) char sm[2 * ATILE + 2 * BTILE];

    const uint32_t smb = smem_to_u32(sm);
    const int tid  = threadIdx.x;
    const int wid  = tid >> 5;
    const int lane = tid & 31;

    A += (long long)blockIdx.z * batchA;
    B += (long long)blockIdx.z * batchB;
    C += (long long)blockIdx.z * batchC;
    const int bm = blockIdx.y * 128;
    const int bn = blockIdx.x * BN;

    const int wm = (wid & 3) * 32;
    const int wn = (wid >> 2) * WN;

    float acc[2][2 * NG][4];
#pragma unroll
    for (int i = 0; i < 2; i++)
#pragma unroll
        for (int j = 0; j < 2 * NG; j++)
#pragma unroll
            for (int r = 0; r < 4; r++) acc[i][j][r] = 0.0f;

    const int lr = tid >> 2;           // 0..63 loader row
    const int lq = tid & 3;            // 16B quad within 64B row chunk
    const int nIter = 3 * segIters;

    // ---- async tile loader (A: 128 rows, B: BN rows; 64B per row) ----
    auto load_tiles = [&](int it, int s) {
        const int seg  = it / segIters;
        const int koff = seg * segStride + (it - seg * segIters) * 32;
        const uint32_t abuf = smb + s * ATILE;
        const uint32_t bbuf = smb + 2 * ATILE + s * BTILE;
#pragma unroll
        for (int rr = 0; rr < 128; rr += 64) {
            CP_ASYNC16(abuf + (lr + rr) * SA + lq * 16,
                       A + (size_t)(bm + lr + rr) * lda + koff + lq * 8);
        }
#pragma unroll
        for (int rr = 0; rr < BN; rr += 64) {
            CP_ASYNC16(bbuf + (lr + rr) * SA + lq * 16,
                       B + (size_t)(bn + lr + rr) * ldb + koff + lq * 8);
        }
        CP_COMMIT();
    };

    load_tiles(0, 0);

    for (int it = 0; it < nIter; ++it) {
        const int s = it & 1;
        if (it + 1 < nIter) { load_tiles(it + 1, s ^ 1); CP_WAIT(1); }
        else                { CP_WAIT(0); }
        __syncthreads();

        const uint32_t abuf = smb + s * ATILE;
        const uint32_t bbuf = smb + 2 * ATILE + s * BTILE;
        const int lrow = lane & 15;
        const int lcol = (lane >> 4) * 16;

#pragma unroll
        for (int kk = 0; kk < 2; ++kk) {
            uint32_t a[2][4];
#pragma unroll
            for (int mf = 0; mf < 2; ++mf) {
                LDMATRIX_X4(a[mf][0], a[mf][1], a[mf][2], a[mf][3],
                            abuf + (wm + mf * 16 + lrow) * SA + kk * 32 + lcol);
            }
#pragma unroll
            for (int g = 0; g < NG; ++g) {
                uint32_t b0, b1, b2, b3;
                LDMATRIX_X4(b0, b1, b2, b3,
                            bbuf + (wn + g * 16 + lrow) * SA + kk * 32 + lcol);
#pragma unroll
                for (int mf = 0; mf < 2; ++mf) {
                    MMA_16816(acc[mf][2 * g],     a[mf], b0, b2);
                    MMA_16816(acc[mf][2 * g + 1], a[mf], b1, b3);
                }
            }
        }
        __syncthreads();
    }

    // ---- epilogue ----
    const int tq = lane >> 2;          // quad row 0..7
    const int tr = lane & 3;           // pair col 0..3
#pragma unroll
    for (int mf = 0; mf < 2; ++mf) {
        const int row0 = bm + wm + mf * 16 + tq;
#pragma unroll
        for (int nf = 0; nf < 2 * NG; ++nf) {
            const int col = bn + wn + nf * 8 + tr * 2;
            float bx = 0.0f, by = 0.0f;
            if (bias) { bx = bias[col]; by = bias[col + 1]; }
#pragma unroll
            for (int hh = 0; hh < 2; ++hh) {
                const int row = row0 + hh * 8;
                float vx = acc[mf][nf][2 * hh]     * alpha + bx;
                float vy = acc[mf][nf][2 * hh + 1] * alpha + by;
                if (ACT == 1) { vx = gelu_f(vx); vy = gelu_f(vy); }
                float2 o = make_float2(vx, vy);
                *(float2*)(C + (size_t)row * ldc + col) = o;
            }
        }
    }
}

// ===================== packing kernels ======================================
// fp32 [M,K] row-major -> bf16 [M,3K] packed [hi | lo | hi]  (A-side)
__global__ __launch_bounds__(256)
void pack_act(const float* __restrict__ in, __nv_bfloat16* __restrict__ out,
              int K, long long inB, long long outB)
{
    in  += (long long)blockIdx.z * inB;
    out += (long long)blockIdx.z * outB;
    const int k = blockIdx.x * 256 + threadIdx.x;
    const int r = blockIdx.y;
    const float v = in[(size_t)r * K + k];
    const __nv_bfloat16 hi = __float2bfloat16_rn(v);
    const __nv_bfloat16 lo = __float2bfloat16_rn(v - __bfloat162float(hi));
    const size_t o = (size_t)r * 3 * K;
    out[o + k]         = hi;
    out[o + K + k]     = lo;
    out[o + 2 * K + k] = hi;
}

// fp32 [M,K] row-major -> bf16 [M,3K] packed [hi | hi | lo]  (B-side)
// (pairs with pack_act so seg products are hi*hi + lo*hi + hi*lo)
__global__ __launch_bounds__(256)
void pack_act_w(const float* __restrict__ in, __nv_bfloat16* __restrict__ out,
                int K, long long inB, long long outB)
{
    in  += (long long)blockIdx.z * inB;
    out += (long long)blockIdx.z * outB;
    const int k = blockIdx.x * 256 + threadIdx.x;
    const int r = blockIdx.y;
    const float v = in[(size_t)r * K + k];
    const __nv_bfloat16 hi = __float2bfloat16_rn(v);
    const __nv_bfloat16 lo = __float2bfloat16_rn(v - __bfloat162float(hi));
    const size_t o = (size_t)r * 3 * K;
    out[o + k]         = hi;
    out[o + K + k]     = hi;
    out[o + 2 * K + k] = lo;
}

// fp32 in[K,N] (ld=ldIn) -> bf16 out[N,3K] packed [hi | hi | lo]  (B-side)
__global__ __launch_bounds__(256)
void pack_wT(const float* __restrict__ in, int ldIn, long long inB,
             __nv_bfloat16* __restrict__ out, int K, long long outB)
{
    __shared__ float t[32][33];
    in  += (long long)blockIdx.z * inB;
    out += (long long)blockIdx.z * outB;
    const int k0 = blockIdx.y * 32;
    const int n0 = blockIdx.x * 32;
    const int tx = threadIdx.x & 31;
    const int ty = threadIdx.x >> 5;     // 0..7
#pragma unroll
    for (int i = 0; i < 32; i += 8)
        t[ty + i][tx] = in[(size_t)(k0 + ty + i) * ldIn + n0 + tx];
    __syncthreads();
#pragma unroll
    for (int i = 0; i < 32; i += 8) {
        const float v = t[tx][ty + i];                 // in[k0+tx][n0+ty+i]
        const __nv_bfloat16 hi = __float2bfloat16_rn(v);
        const __nv_bfloat16 lo = __float2bfloat16_rn(v - __bfloat162float(hi));
        const size_t o = (size_t)(n0 + ty + i) * 3 * K;
        out[o + k0 + tx]         = hi;
        out[o + K + k0 + tx]     = hi;
        out[o + 2 * K + k0 + tx] = lo;
    }
}

// ===================== softmax over rows of length SEQ ======================
__global__ __launch_bounds__(256) void softmax_kernel(float* __restrict__ att)
{
    __shared__ float red[8];
    float* row = att + (size_t)blockIdx.x * SEQ;
    const int tid = threadIdx.x;
    const int lane = tid & 31, wid = tid >> 5;

    float4 a = ((const float4*)row)[tid * 2];
    float4 b = ((const float4*)row)[tid * 2 + 1];

    float m = fmaxf(fmaxf(fmaxf(a.x, a.y), fmaxf(a.z, a.w)),
                    fmaxf(fmaxf(b.x, b.y), fmaxf(b.z, b.w)));
#pragma unroll
    for (int o = 16; o > 0; o >>= 1) m = fmaxf(m, __shfl_xor_sync(0xffffffffu, m, o));
    if (lane == 0) red[wid] = m;
    __syncthreads();
    float bmax = red[0];
#pragma unroll
    for (int i = 1; i < 8; i++) bmax = fmaxf(bmax, red[i]);
    __syncthreads();

    a.x = __expf(a.x - bmax); a.y = __expf(a.y - bmax);
    a.z = __expf(a.z - bmax); a.w = __expf(a.w - bmax);
    b.x = __expf(b.x - bmax); b.y = __expf(b.y - bmax);
    b.z = __expf(b.z - bmax); b.w = __expf(b.w - bmax);

    float s = a.x + a.y + a.z + a.w + b.x + b.y + b.z + b.w;
#pragma unroll
    for (int o = 16; o > 0; o >>= 1) s += __shfl_xor_sync(0xffffffffu, s, o);
    if (lane == 0) red[wid] = s;
    __syncthreads();
    float total = 0.0f;
#pragma unroll
    for (int i = 0; i < 8; i++) total += red[i];
    const float inv = 1.0f / total;

    a.x *= inv; a.y *= inv; a.z *= inv; a.w *= inv;
    b.x *= inv; b.y *= inv; b.z *= inv; b.w *= inv;
    ((float4*)row)[tid * 2]     = a;
    ((float4*)row)[tid * 2 + 1] = b;
}

// ===================== fused residual add + LayerNorm =======================
__global__ __launch_bounds__(256) void add_ln_kernel(
    float* __restrict__ x, const float* __restrict__ res,
    const float* __restrict__ g, const float* __restrict__ b)
{
    __shared__ float red[8];
    const size_t base = (size_t)blockIdx.x * D_MODEL;
    const int tid = threadIdx.x;
    const int lane = tid & 31, wid = tid >> 5;

    float4 xv = *(const float4*)&x[base + tid * 4];
    float4 rv = *(const float4*)&res[base + tid * 4];
    float v0 = xv.x + rv.x, v1 = xv.y + rv.y, v2 = xv.z + rv.z, v3 = xv.w + rv.w;

    float s = v0 + v1 + v2 + v3;
#pragma unroll
    for (int o = 16; o > 0; o >>= 1) s += __shfl_xor_sync(0xffffffffu, s, o);
    if (lane == 0) red[wid] = s;
    __syncthreads();
    float tot = 0.0f;
#pragma unroll
    for (int i = 0; i < 8; i++) tot += red[i];
    const float mu = tot * (1.0f / D_MODEL);
    __syncthreads();

    float d0 = v0 - mu, d1 = v1 - mu, d2 = v2 - mu, d3 = v3 - mu;
    float s2 = d0 * d0 + d1 * d1 + d2 * d2 + d3 * d3;
#pragma unroll
    for (int o = 16; o > 0; o >>= 1) s2 += __shfl_xor_sync(0xffffffffu, s2, o);
    if (lane == 0) red[wid] = s2;
    __syncthreads();
    float tot2 = 0.0f;
#pragma unroll
    for (int i = 0; i < 8; i++) tot2 += red[i];
    const float rs = rsqrtf(tot2 * (1.0f / D_MODEL) + 1e-5f);

    const int c = tid * 4;
    float4 gg = *(const float4*)&g[c];
    float4 bb = *(const float4*)&b[c];
    float4 out;
    out.x = d0 * rs * gg.x + bb.x;
    out.y = d1 * rs * gg.y + bb.y;
    out.z = d2 * rs * gg.z + bb.z;
    out.w = d3 * rs * gg.w + bb.w;
    *(float4*)&x[base + c] = out;
}

// ===================== host =================================================
extern "C" void kernel_launch(void* const* d_in, const int* in_sizes, int n_in,
                              void* d_out, int out_size)
{
    const float* x_in = (const float*)d_in[0];
    const float* wq = (const float*)d_in[1];
    const float* bq = (const float*)d_in[2];
    const float* wk = (const float*)d_in[3];
    const float* bk = (const float*)d_in[4];
    const float* wv = (const float*)d_in[5];
    const float* bv = (const float*)d_in[6];
    const float* wo = (const float*)d_in[7];
    const float* bo = (const float*)d_in[8];
    const float* w1 = (const float*)d_in[9];
    const float* b1 = (const float*)d_in[10];
    const float* w2 = (const float*)d_in[11];
    const float* b2 = (const float*)d_in[12];
    const float* ln1g = (const float*)d_in[13];
    const float* ln1b = (const float*)d_in[14];
    const float* ln2g = (const float*)d_in[15];
    const float* ln2b = (const float*)d_in[16];

    float *x, *q, *k, *v, *ctx, *t1, *h, *att;
    __nv_bfloat16 *xp, *qp, *kp, *hp, *pp, *vtp, *wqp, *wkp, *wvp, *wop, *w1p, *w2p;
    cudaGetSymbolAddress((void**)&x,   g_x);
    cudaGetSymbolAddress((void**)&q,   g_q);
    cudaGetSymbolAddress((void**)&k,   g_k);
    cudaGetSymbolAddress((void**)&v,   g_v);
    cudaGetSymbolAddress((void**)&ctx, g_ctx);
    cudaGetSymbolAddress((void**)&t1,  g_t1);
    cudaGetSymbolAddress((void**)&h,   g_h);
    cudaGetSymbolAddress((void**)&att, g_att);
    cudaGetSymbolAddress((void**)&xp,  g_xp);
    cudaGetSymbolAddress((void**)&qp,  g_qp);
    cudaGetSymbolAddress((void**)&kp,  g_kp);
    cudaGetSymbolAddress((void**)&hp,  g_hp);
    cudaGetSymbolAddress((void**)&pp,  g_pp);
    cudaGetSymbolAddress((void**)&vtp, g_vtp);
    cudaGetSymbolAddress((void**)&wqp, g_wqp);
    cudaGetSymbolAddress((void**)&wkp, g_wkp);
    cudaGetSymbolAddress((void**)&wvp, g_wvp);
    cudaGetSymbolAddress((void**)&wop, g_wop);
    cudaGetSymbolAddress((void**)&w1p, g_w1p);
    cudaGetSymbolAddress((void**)&w2p, g_w2p);

    cudaMemcpyAsync(x, x_in, sizeof(float) * SEQ * D_MODEL,
                    cudaMemcpyDeviceToDevice, 0);

    const dim3 blk(256);

    for (int l = 0; l < NLAYERS; l++) {
        const float* Wq = wq + (size_t)l * D_MODEL * D_MODEL;
        const float* Wk = wk + (size_t)l * D_MODEL * D_MODEL;
        const float* Wv = wv + (size_t)l * D_MODEL * D_MODEL;
        const float* Wo = wo + (size_t)l * D_MODEL * D_MODEL;
        const float* W1 = w1 + (size_t)l * D_MODEL * DFF;
        const float* W2 = w2 + (size_t)l * DFF * D_MODEL;

        // ---- pack weights (transposed, [N,3K], hi|hi|lo) ----
        pack_wT<<<dim3(D_MODEL/32, D_MODEL/32, 1), blk>>>(Wq, D_MODEL, 0, wqp, D_MODEL, 0);
        pack_wT<<<dim3(D_MODEL/32, D_MODEL/32, 1), blk>>>(Wk, D_MODEL, 0, wkp, D_MODEL, 0);
        pack_wT<<<dim3(D_MODEL/32, D_MODEL/32, 1), blk>>>(Wv, D_MODEL, 0, wvp, D_MODEL, 0);
        pack_wT<<<dim3(D_MODEL/32, D_MODEL/32, 1), blk>>>(Wo, D_MODEL, 0, wop, D_MODEL, 0);
        pack_wT<<<dim3(DFF/32,     D_MODEL/32, 1), blk>>>(W1, DFF,     0, w1p, D_MODEL, 0);
        pack_wT<<<dim3(D_MODEL/32, DFF/32,     1), blk>>>(W2, D_MODEL, 0, w2p, DFF,     0);

        // ---- QKV projections ----
        pack_act<<<dim3(D_MODEL/256, SEQ, 1), blk>>>(x, xp, D_MODEL, 0, 0);
        gemm_tc<128, 0><<<dim3(D_MODEL/128, SEQ/128, 1), blk>>>(
            xp, 3*D_MODEL, 0, wqp, 3*D_MODEL, 0, q, D_MODEL, 0,
            bq + (size_t)l * D_MODEL, D_MODEL/32, D_MODEL, 1.0f);
        gemm_tc<128, 0><<<dim3(D_MODEL/128, SEQ/128, 1), blk>>>(
            xp, 3*D_MODEL, 0, wkp, 3*D_MODEL, 0, k, D_MODEL, 0,
            bk + (size_t)l * D_MODEL, D_MODEL/32, D_MODEL, 1.0f);
        gemm_tc<128, 0><<<dim3(D_MODEL/128, SEQ/128, 1), blk>>>(
            xp, 3*D_MODEL, 0, wvp, 3*D_MODEL, 0, v, D_MODEL, 0,
            bv + (size_t)l * D_MODEL, D_MODEL/32, D_MODEL, 1.0f);

        // ---- scores = Q Kt / 8 (per head; segStride addressing) ----
        // Q packed A-side [hi|lo|hi]; K packed B-side [hi|hi|lo] (the R3 bug fix)
        pack_act  <<<dim3(D_MODEL/256, SEQ, 1), blk>>>(q, qp, D_MODEL, 0, 0);
        pack_act_w<<<dim3(D_MODEL/256, SEQ, 1), blk>>>(k, kp, D_MODEL, 0, 0);
        gemm_tc<128, 0><<<dim3(SEQ/128, SEQ/128, NHEAD), blk>>>(
            qp, 3*D_MODEL, DK, kp, 3*D_MODEL, DK,
            att, SEQ, (long long)SEQ * SEQ, nullptr, DK/32, D_MODEL, 0.125f);

        softmax_kernel<<<NHEAD * SEQ, blk>>>(att);

        // ---- ctx = P V (per head) ----
        pack_act<<<dim3(SEQ/256, SEQ, NHEAD), blk>>>(
            att, pp, SEQ, (long long)SEQ * SEQ, (long long)SEQ * 3 * SEQ);
        pack_wT<<<dim3(DK/32, SEQ/32, NHEAD), blk>>>(
            v, D_MODEL, DK, vtp, SEQ, (long long)DK * 3 * SEQ);
        gemm_tc<64, 0><<<dim3(1, SEQ/128, NHEAD), blk>>>(
            pp, 3*SEQ, (long long)SEQ * 3 * SEQ, vtp, 3*SEQ, (long long)DK * 3 * SEQ,
            ctx, D_MODEL, DK, nullptr, SEQ/32, SEQ, 1.0f);

        // ---- output projection + LN1 ----
        pack_act<<<dim3(D_MODEL/256, SEQ, 1), blk>>>(ctx, qp, D_MODEL, 0, 0);
        gemm_tc<128, 0><<<dim3(D_MODEL/128, SEQ/128, 1), blk>>>(
            qp, 3*D_MODEL, 0, wop, 3*D_MODEL, 0, t1, D_MODEL, 0,
            bo + (size_t)l * D_MODEL, D_MODEL/32, D_MODEL, 1.0f);
        add_ln_kernel<<<SEQ, blk>>>(x, t1,
            ln1g + (size_t)l * D_MODEL, ln1b + (size_t)l * D_MODEL);

        // ---- FFN ----
        pack_act<<<dim3(D_MODEL/256, SEQ, 1), blk>>>(x, xp, D_MODEL, 0, 0);
        gemm_tc<128, 1><<<dim3(DFF/128, SEQ/128, 1), blk>>>(
            xp, 3*D_MODEL, 0, w1p, 3*D_MODEL, 0, h, DFF, 0,
            b1 + (size_t)l * DFF, D_MODEL/32, D_MODEL, 1.0f);
        pack_act<<<dim3(DFF/256, SEQ, 1), blk>>>(h, hp, DFF, 0, 0);
        gemm_tc<128, 0><<<dim3(D_MODEL/128, SEQ/128, 1), blk>>>(
            hp, 3*DFF, 0, w2p, 3*DFF, 0, t1, D_MODEL, 0,
            b2 + (size_t)l * D_MODEL, DFF/32, DFF, 1.0f);
        add_ln_kernel<<<SEQ, blk>>>(x, t1,
            ln2g + (size_t)l * D_MODEL, ln2b + (size_t)l * D_MODEL);
    }

    cudaMemcpyAsync(d_out, x, sizeof(float) * SEQ * D_MODEL,
                    cudaMemcpyDeviceToDevice, 0);
}

// round 6
// speedup vs baseline: 2.3872x; 1.5364x over previous
#include <cuda_runtime.h>
#include <cuda_bf16.h>
#include <math.h>
#include <stdint.h>

#define D_MODEL 1024
#define SEQ     2048
#define NHEAD   16
#define DK      64
#define DFF     4096
#define NLAYERS 4

// ===================== scratch (static device globals) ======================
__device__ float g_x  [SEQ * D_MODEL];
__device__ float g_ctx[SEQ * D_MODEL];
__device__ float g_t1 [SEQ * D_MODEL];
__device__ float g_h  [SEQ * DFF];

// packed split-bf16 operands
// A-side "act": [hi(K) | lo(K) | hi(K)] ; B-side "wgt": [hi(K) | hi(K) | lo(K)]
__device__ __nv_bfloat16 g_xp [(size_t)SEQ * 3 * D_MODEL];
__device__ __nv_bfloat16 g_hp [(size_t)SEQ * 3 * DFF];
__device__ __nv_bfloat16 g_wqp[(size_t)D_MODEL * 3 * D_MODEL];
__device__ __nv_bfloat16 g_wkp[(size_t)D_MODEL * 3 * D_MODEL];
__device__ __nv_bfloat16 g_wvp[(size_t)D_MODEL * 3 * D_MODEL];
__device__ __nv_bfloat16 g_wop[(size_t)D_MODEL * 3 * D_MODEL];
__device__ __nv_bfloat16 g_w1p[(size_t)DFF * 3 * D_MODEL];
__device__ __nv_bfloat16 g_w2p[(size_t)D_MODEL * 3 * DFF];

// head-major bf16 Q/K/V for flash attention: [H][SEQ][DK]
__device__ __nv_bfloat16 g_qb [(size_t)NHEAD * SEQ * DK];
__device__ __nv_bfloat16 g_kb [(size_t)NHEAD * SEQ * DK];
__device__ __nv_bfloat16 g_vb [(size_t)NHEAD * SEQ * DK];

// ===================== helpers =============================================
__device__ __forceinline__ uint32_t smem_to_u32(const void* p) {
    uint32_t a;
    asm("{ .reg .u64 t; cvta.to.shared.u64 t, %1; cvt.u32.u64 %0, t; }"
        : "=r"(a) : "l"(p));
    return a;
}

__device__ __forceinline__ float gelu_f(float x) {
    const float c = 0.7978845608028654f;
    float t = tanhf(c * (x + 0.044715f * x * x * x));
    return 0.5f * x * (1.0f + t);
}

#define CP_ASYNC16(dst, src) \
    asm volatile("cp.async.cg.shared.global [%0], [%1], 16;" \
        :: "r"(dst), "l"(src) : "memory")
#define CP_COMMIT() asm volatile("cp.async.commit_group;" ::: "memory")
#define CP_WAIT(N)  asm volatile("cp.async.wait_group %0;" :: "n"(N) : "memory")

#define LDMATRIX_X4(r0, r1, r2, r3, addr) \
    asm volatile("ldmatrix.sync.aligned.m8n8.x4.shared.b16 {%0,%1,%2,%3}, [%4];" \
        : "=r"(r0), "=r"(r1), "=r"(r2), "=r"(r3) : "r"(addr))

#define LDMATRIX_X4_T(r0, r1, r2, r3, addr) \
    asm volatile("ldmatrix.sync.aligned.m8n8.x4.trans.shared.b16 {%0,%1,%2,%3}, [%4];" \
        : "=r"(r0), "=r"(r1), "=r"(r2), "=r"(r3) : "r"(addr))

#define MMA_16816(c, a, b0, b1) \
    asm volatile("mma.sync.aligned.m16n8k16.row.col.f32.bf16.bf16.f32 " \
        "{%0,%1,%2,%3}, {%4,%5,%6,%7}, {%8,%9}, {%0,%1,%2,%3};" \
        : "+f"((c)[0]), "+f"((c)[1]), "+f"((c)[2]), "+f"((c)[3]) \
        : "r"((a)[0]), "r"((a)[1]), "r"((a)[2]), "r"((a)[3]), \
          "r"(b0), "r"(b1))

// ===================== HMMA split-bf16 GEMM =================================
// ACT: 0 = fp32 out (alpha pre-bias), 1 = fp32 + GELU, 2 = bf16 head-major
//      out[((col/64)*SEQ + row)*64 + col%64] = bf16((acc + bias) * alpha)
#define SA 80   // padded smem row stride bytes (40 bf16) -> LDSM conflict-free

template <int BN, int ACT>
__global__ __launch_bounds__(256)
void gemm_tc(const __nv_bfloat16* __restrict__ A, int lda, long long batchA,
             const __nv_bfloat16* __restrict__ B, int ldb, long long batchB,
             float* __restrict__ C, int ldc, long long batchC,
             const float* __restrict__ bias, int segIters, int segStride,
             float alpha)
{
    constexpr int WN    = BN / 2;      // warp n-tile (warps laid out 4m x 2n)
    constexpr int NG    = WN / 16;     // ldmatrix.x4 groups per warp
    constexpr int ATILE = 128 * SA;
    constexpr int BTILE = BN * SA;
    __shared__ __align__(16) char sm[2 * ATILE + 2 * BTILE];

    const uint32_t smb = smem_to_u32(sm);
    const int tid  = threadIdx.x;
    const int wid  = tid >> 5;
    const int lane = tid & 31;

    A += (long long)blockIdx.z * batchA;
    B += (long long)blockIdx.z * batchB;
    C += (long long)blockIdx.z * batchC;
    const int bm = blockIdx.y * 128;
    const int bn = blockIdx.x * BN;

    const int wm = (wid & 3) * 32;
    const int wn = (wid >> 2) * WN;

    float acc[2][2 * NG][4];
#pragma unroll
    for (int i = 0; i < 2; i++)
#pragma unroll
        for (int j = 0; j < 2 * NG; j++)
#pragma unroll
            for (int r = 0; r < 4; r++) acc[i][j][r] = 0.0f;

    const int lr = tid >> 2;
    const int lq = tid & 3;
    const int nIter = 3 * segIters;

    auto load_tiles = [&](int it, int s) {
        const int seg  = it / segIters;
        const int koff = seg * segStride + (it - seg * segIters) * 32;
        const uint32_t abuf = smb + s * ATILE;
        const uint32_t bbuf = smb + 2 * ATILE + s * BTILE;
#pragma unroll
        for (int rr = 0; rr < 128; rr += 64) {
            CP_ASYNC16(abuf + (lr + rr) * SA + lq * 16,
                       A + (size_t)(bm + lr + rr) * lda + koff + lq * 8);
        }
#pragma unroll
        for (int rr = 0; rr < BN; rr += 64) {
            CP_ASYNC16(bbuf + (lr + rr) * SA + lq * 16,
                       B + (size_t)(bn + lr + rr) * ldb + koff + lq * 8);
        }
        CP_COMMIT();
    };

    load_tiles(0, 0);

    for (int it = 0; it < nIter; ++it) {
        const int s = it & 1;
        if (it + 1 < nIter) { load_tiles(it + 1, s ^ 1); CP_WAIT(1); }
        else                { CP_WAIT(0); }
        __syncthreads();

        const uint32_t abuf = smb + s * ATILE;
        const uint32_t bbuf = smb + 2 * ATILE + s * BTILE;
        const int lrow = lane & 15;
        const int lcol = (lane >> 4) * 16;

#pragma unroll
        for (int kk = 0; kk < 2; ++kk) {
            uint32_t a[2][4];
#pragma unroll
            for (int mf = 0; mf < 2; ++mf) {
                LDMATRIX_X4(a[mf][0], a[mf][1], a[mf][2], a[mf][3],
                            abuf + (wm + mf * 16 + lrow) * SA + kk * 32 + lcol);
            }
#pragma unroll
            for (int g = 0; g < NG; ++g) {
                uint32_t b0, b1, b2, b3;
                LDMATRIX_X4(b0, b1, b2, b3,
                            bbuf + (wn + g * 16 + lrow) * SA + kk * 32 + lcol);
#pragma unroll
                for (int mf = 0; mf < 2; ++mf) {
                    MMA_16816(acc[mf][2 * g],     a[mf], b0, b2);
                    MMA_16816(acc[mf][2 * g + 1], a[mf], b1, b3);
                }
            }
        }
        __syncthreads();
    }

    // ---- epilogue ----
    const int tq = lane >> 2;
    const int tr = lane & 3;
#pragma unroll
    for (int mf = 0; mf < 2; ++mf) {
        const int row0 = bm + wm + mf * 16 + tq;
#pragma unroll
        for (int nf = 0; nf < 2 * NG; ++nf) {
            const int col = bn + wn + nf * 8 + tr * 2;
            float bx = 0.0f, by = 0.0f;
            if (bias) { bx = bias[col]; by = bias[col + 1]; }
#pragma unroll
            for (int hh = 0; hh < 2; ++hh) {
                const int row = row0 + hh * 8;
                if (ACT == 2) {
                    float vx = (acc[mf][nf][2 * hh]     + bx) * alpha;
                    float vy = (acc[mf][nf][2 * hh + 1] + by) * alpha;
                    __nv_bfloat162 p = __floats2bfloat162_rn(vx, vy);
                    __nv_bfloat16* Cb = (__nv_bfloat16*)C;
                    const size_t idx =
                        ((size_t)(col >> 6) * SEQ + row) * DK + (col & 63);
                    *(uint32_t*)&Cb[idx] = *(uint32_t*)&p;
                } else {
                    float vx = acc[mf][nf][2 * hh]     * alpha + bx;
                    float vy = acc[mf][nf][2 * hh + 1] * alpha + by;
                    if (ACT == 1) { vx = gelu_f(vx); vy = gelu_f(vy); }
                    *(float2*)(C + (size_t)row * ldc + col) =
                        make_float2(vx, vy);
                }
            }
        }
    }
}

// ===================== flash attention ======================================
// One CTA = one head (blockIdx.y), one 128-row query block (blockIdx.x).
// 8 warps; warp w owns query rows [w*16, w*16+16). Online softmax in regs.
#define FSTR 144   // 64 bf16 = 128B + 16B pad (odd 16B multiple -> no conflicts)

__global__ __launch_bounds__(256, 1)
void flash_attn(const __nv_bfloat16* __restrict__ Qb,   // [H][SEQ][DK], pre-scaled by 1/8
                const __nv_bfloat16* __restrict__ Kb,
                const __nv_bfloat16* __restrict__ Vb,
                float* __restrict__ Ctx)                // [SEQ][D_MODEL]
{
    extern __shared__ __align__(16) char sm[];
    const uint32_t smb = smem_to_u32(sm);
    const uint32_t Qs  = smb;                     // 128*FSTR
    const uint32_t KsB = smb + 128 * FSTR;        // 2 buffers
    const uint32_t VsB = smb + 3 * 128 * FSTR;    // 2 buffers

    const int tid  = threadIdx.x;
    const int wid  = tid >> 5;
    const int lane = tid & 31;
    const int qb   = blockIdx.x;
    const int h    = blockIdx.y;

    const __nv_bfloat16* Qh = Qb + ((size_t)h * SEQ + qb * 128) * DK;
    const __nv_bfloat16* Kh = Kb + (size_t)h * SEQ * DK;
    const __nv_bfloat16* Vh = Vb + (size_t)h * SEQ * DK;

    // ---- stage Q tile (128 x 64 bf16) ----
#pragma unroll
    for (int i = 0; i < 4; i++) {
        const int idx = tid + i * 256;            // 1024 chunks of 16B
        const int r = idx >> 3, c = idx & 7;
        *(float4*)(sm + r * FSTR + c * 16) =
            *(const float4*)(Qh + (size_t)r * DK + c * 8);
    }
    __syncthreads();

    // ---- Q fragments (16 rows x 64 cols per warp) ----
    const int lrow  = lane & 15;
    const int lcolb = (lane >> 4) * 16;
    uint32_t qf[4][4];
#pragma unroll
    for (int kc = 0; kc < 4; kc++)
        LDMATRIX_X4(qf[kc][0], qf[kc][1], qf[kc][2], qf[kc][3],
                    Qs + (wid * 16 + lrow) * FSTR + kc * 32 + lcolb);

    // ---- K/V tile async loader ----
    auto load_kv = [&](int kb, int s) {
        const uint32_t kd = KsB + s * 128 * FSTR;
        const uint32_t vd = VsB + s * 128 * FSTR;
#pragma unroll
        for (int i = 0; i < 4; i++) {
            const int idx = tid + i * 256;
            const int r = idx >> 3, c = idx & 7;
            CP_ASYNC16(kd + r * FSTR + c * 16,
                       Kh + (size_t)(kb * 128 + r) * DK + c * 8);
            CP_ASYNC16(vd + r * FSTR + c * 16,
                       Vh + (size_t)(kb * 128 + r) * DK + c * 8);
        }
        CP_COMMIT();
    };

    float m0 = -1e30f, m1 = -1e30f, l0 = 0.0f, l1 = 0.0f;
    float ctxa[8][4];
#pragma unroll
    for (int i = 0; i < 8; i++)
#pragma unroll
        for (int j = 0; j < 4; j++) ctxa[i][j] = 0.0f;

    load_kv(0, 0);

    for (int kb = 0; kb < SEQ / 128; ++kb) {
        const int s = kb & 1;
        if (kb + 1 < SEQ / 128) { load_kv(kb + 1, s ^ 1); CP_WAIT(1); }
        else                    { CP_WAIT(0); }
        __syncthreads();

        const uint32_t Ks = KsB + s * 128 * FSTR;
        const uint32_t Vs = VsB + s * 128 * FSTR;

        // ---- S = Q K^T (16 x 128 per warp), scores pre-scaled ----
        float sacc[16][4];
#pragma unroll
        for (int i = 0; i < 16; i++)
#pragma unroll
            for (int j = 0; j < 4; j++) sacc[i][j] = 0.0f;

#pragma unroll
        for (int kc = 0; kc < 4; kc++) {
#pragma unroll
            for (int ng = 0; ng < 8; ng++) {
                uint32_t b0, b1, b2, b3;
                LDMATRIX_X4(b0, b1, b2, b3,
                            Ks + (ng * 16 + lrow) * FSTR + kc * 32 + lcolb);
                MMA_16816(sacc[2 * ng],     qf[kc], b0, b2);
                MMA_16816(sacc[2 * ng + 1], qf[kc], b1, b3);
            }
        }

        // ---- online softmax update ----
        float mn0 = -1e30f, mn1 = -1e30f;
#pragma unroll
        for (int f = 0; f < 16; f++) {
            mn0 = fmaxf(mn0, fmaxf(sacc[f][0], sacc[f][1]));
            mn1 = fmaxf(mn1, fmaxf(sacc[f][2], sacc[f][3]));
        }
        mn0 = fmaxf(mn0, __shfl_xor_sync(0xffffffffu, mn0, 1));
        mn0 = fmaxf(mn0, __shfl_xor_sync(0xffffffffu, mn0, 2));
        mn1 = fmaxf(mn1, __shfl_xor_sync(0xffffffffu, mn1, 1));
        mn1 = fmaxf(mn1, __shfl_xor_sync(0xffffffffu, mn1, 2));

        const float mN0 = fmaxf(m0, mn0);
        const float mN1 = fmaxf(m1, mn1);
        const float c0 = __expf(m0 - mN0);
        const float c1 = __expf(m1 - mN1);

        float rs0 = 0.0f, rs1 = 0.0f;
        uint32_t pl[16], ph[16];
#pragma unroll
        for (int f = 0; f < 16; f++) {
            const float e0 = __expf(sacc[f][0] - mN0);
            const float e1 = __expf(sacc[f][1] - mN0);
            const float e2 = __expf(sacc[f][2] - mN1);
            const float e3 = __expf(sacc[f][3] - mN1);
            rs0 += e0 + e1;
            rs1 += e2 + e3;
            __nv_bfloat162 t0 = __floats2bfloat162_rn(e0, e1);
            __nv_bfloat162 t1 = __floats2bfloat162_rn(e2, e3);
            pl[f] = *(uint32_t*)&t0;
            ph[f] = *(uint32_t*)&t1;
        }
        rs0 += __shfl_xor_sync(0xffffffffu, rs0, 1);
        rs0 += __shfl_xor_sync(0xffffffffu, rs0, 2);
        rs1 += __shfl_xor_sync(0xffffffffu, rs1, 1);
        rs1 += __shfl_xor_sync(0xffffffffu, rs1, 2);

        l0 = l0 * c0 + rs0;
        l1 = l1 * c1 + rs1;
        m0 = mN0;
        m1 = mN1;
#pragma unroll
        for (int nf = 0; nf < 8; nf++) {
            ctxa[nf][0] *= c0; ctxa[nf][1] *= c0;
            ctxa[nf][2] *= c1; ctxa[nf][3] *= c1;
        }

        // ---- ctx += P V ----
#pragma unroll
        for (int kc = 0; kc < 8; kc++) {
            uint32_t ap[4] = { pl[2 * kc], ph[2 * kc],
                               pl[2 * kc + 1], ph[2 * kc + 1] };
#pragma unroll
            for (int vg = 0; vg < 4; vg++) {
                uint32_t r0, r1, r2, r3;
                LDMATRIX_X4_T(r0, r1, r2, r3,
                              Vs + (kc * 16 + lrow) * FSTR + vg * 32 + lcolb);
                MMA_16816(ctxa[2 * vg],     ap, r0, r1);
                MMA_16816(ctxa[2 * vg + 1], ap, r2, r3);
            }
        }
        __syncthreads();
    }

    // ---- epilogue: ctx / l -> Ctx[row][h*64 + col] ----
    const float il0 = 1.0f / l0;
    const float il1 = 1.0f / l1;
    const int row0 = qb * 128 + wid * 16 + (lane >> 2);
    const int colb = h * DK + (lane & 3) * 2;
#pragma unroll
    for (int nf = 0; nf < 8; nf++) {
        const int col = colb + nf * 8;
        *(float2*)(Ctx + (size_t)row0 * D_MODEL + col) =
            make_float2(ctxa[nf][0] * il0, ctxa[nf][1] * il0);
        *(float2*)(Ctx + (size_t)(row0 + 8) * D_MODEL + col) =
            make_float2(ctxa[nf][2] * il1, ctxa[nf][3] * il1);
    }
}

// ===================== packing kernels ======================================
// fp32 [M,K] row-major -> bf16 [M,3K] packed [hi | lo | hi]  (A-side)
__global__ __launch_bounds__(256)
void pack_act(const float* __restrict__ in, __nv_bfloat16* __restrict__ out,
              int K, long long inB, long long outB)
{
    in  += (long long)blockIdx.z * inB;
    out += (long long)blockIdx.z * outB;
    const int k = blockIdx.x * 256 + threadIdx.x;
    const int r = blockIdx.y;
    const float v = in[(size_t)r * K + k];
    const __nv_bfloat16 hi = __float2bfloat16_rn(v);
    const __nv_bfloat16 lo = __float2bfloat16_rn(v - __bfloat162float(hi));
    const size_t o = (size_t)r * 3 * K;
    out[o + k]         = hi;
    out[o + K + k]     = lo;
    out[o + 2 * K + k] = hi;
}

// fp32 in[K,N] (ld=ldIn) -> bf16 out[N,3K] packed [hi | hi | lo]  (B-side)
__global__ __launch_bounds__(256)
void pack_wT(const float* __restrict__ in, int ldIn, long long inB,
             __nv_bfloat16* __restrict__ out, int K, long long outB)
{
    __shared__ float t[32][33];
    in  += (long long)blockIdx.z * inB;
    out += (long long)blockIdx.z * outB;
    const int k0 = blockIdx.y * 32;
    const int n0 = blockIdx.x * 32;
    const int tx = threadIdx.x & 31;
    const int ty = threadIdx.x >> 5;
#pragma unroll
    for (int i = 0; i < 32; i += 8)
        t[ty + i][tx] = in[(size_t)(k0 + ty + i) * ldIn + n0 + tx];
    __syncthreads();
#pragma unroll
    for (int i = 0; i < 32; i += 8) {
        const float v = t[tx][ty + i];
        const __nv_bfloat16 hi = __float2bfloat16_rn(v);
        const __nv_bfloat16 lo = __float2bfloat16_rn(v - __bfloat162float(hi));
        const size_t o = (size_t)(n0 + ty + i) * 3 * K;
        out[o + k0 + tx]         = hi;
        out[o + K + k0 + tx]     = hi;
        out[o + 2 * K + k0 + tx] = lo;
    }
}

// ===================== fused residual add + LayerNorm =======================
__global__ __launch_bounds__(256) void add_ln_kernel(
    float* __restrict__ x, const float* __restrict__ res,
    const float* __restrict__ g, const float* __restrict__ b)
{
    __shared__ float red[8];
    const size_t base = (size_t)blockIdx.x * D_MODEL;
    const int tid = threadIdx.x;
    const int lane = tid & 31, wid = tid >> 5;

    float4 xv = *(const float4*)&x[base + tid * 4];
    float4 rv = *(const float4*)&res[base + tid * 4];
    float v0 = xv.x + rv.x, v1 = xv.y + rv.y, v2 = xv.z + rv.z, v3 = xv.w + rv.w;

    float s = v0 + v1 + v2 + v3;
#pragma unroll
    for (int o = 16; o > 0; o >>= 1) s += __shfl_xor_sync(0xffffffffu, s, o);
    if (lane == 0) red[wid] = s;
    __syncthreads();
    float tot = 0.0f;
#pragma unroll
    for (int i = 0; i < 8; i++) tot += red[i];
    const float mu = tot * (1.0f / D_MODEL);
    __syncthreads();

    float d0 = v0 - mu, d1 = v1 - mu, d2 = v2 - mu, d3 = v3 - mu;
    float s2 = d0 * d0 + d1 * d1 + d2 * d2 + d3 * d3;
#pragma unroll
    for (int o = 16; o > 0; o >>= 1) s2 += __shfl_xor_sync(0xffffffffu, s2, o);
    if (lane == 0) red[wid] = s2;
    __syncthreads();
    float tot2 = 0.0f;
#pragma unroll
    for (int i = 0; i < 8; i++) tot2 += red[i];
    const float rs = rsqrtf(tot2 * (1.0f / D_MODEL) + 1e-5f);

    const int c = tid * 4;
    float4 gg = *(const float4*)&g[c];
    float4 bb = *(const float4*)&b[c];
    float4 out;
    out.x = d0 * rs * gg.x + bb.x;
    out.y = d1 * rs * gg.y + bb.y;
    out.z = d2 * rs * gg.z + bb.z;
    out.w = d3 * rs * gg.w + bb.w;
    *(float4*)&x[base + c] = out;
}

// ===================== host =================================================
extern "C" void kernel_launch(void* const* d_in, const int* in_sizes, int n_in,
                              void* d_out, int out_size)
{
    const float* x_in = (const float*)d_in[0];
    const float* wq = (const float*)d_in[1];
    const float* bq = (const float*)d_in[2];
    const float* wk = (const float*)d_in[3];
    const float* bk = (const float*)d_in[4];
    const float* wv = (const float*)d_in[5];
    const float* bv = (const float*)d_in[6];
    const float* wo = (const float*)d_in[7];
    const float* bo = (const float*)d_in[8];
    const float* w1 = (const float*)d_in[9];
    const float* b1 = (const float*)d_in[10];
    const float* w2 = (const float*)d_in[11];
    const float* b2 = (const float*)d_in[12];
    const float* ln1g = (const float*)d_in[13];
    const float* ln1b = (const float*)d_in[14];
    const float* ln2g = (const float*)d_in[15];
    const float* ln2b = (const float*)d_in[16];

    float *x, *ctx, *t1, *h;
    __nv_bfloat16 *xp, *hp, *wqp, *wkp, *wvp, *wop, *w1p, *w2p, *qb, *kb, *vb;
    cudaGetSymbolAddress((void**)&x,   g_x);
    cudaGetSymbolAddress((void**)&ctx, g_ctx);
    cudaGetSymbolAddress((void**)&t1,  g_t1);
    cudaGetSymbolAddress((void**)&h,   g_h);
    cudaGetSymbolAddress((void**)&xp,  g_xp);
    cudaGetSymbolAddress((void**)&hp,  g_hp);
    cudaGetSymbolAddress((void**)&wqp, g_wqp);
    cudaGetSymbolAddress((void**)&wkp, g_wkp);
    cudaGetSymbolAddress((void**)&wvp, g_wvp);
    cudaGetSymbolAddress((void**)&wop, g_wop);
    cudaGetSymbolAddress((void**)&w1p, g_w1p);
    cudaGetSymbolAddress((void**)&w2p, g_w2p);
    cudaGetSymbolAddress((void**)&qb,  g_qb);
    cudaGetSymbolAddress((void**)&kb,  g_kb);
    cudaGetSymbolAddress((void**)&vb,  g_vb);

    const int FLASH_SMEM = 5 * 128 * FSTR;   // Q + 2K + 2V tiles = 92160 B
    cudaFuncSetAttribute(flash_attn,
        cudaFuncAttributeMaxDynamicSharedMemorySize, FLASH_SMEM);

    cudaMemcpyAsync(x, x_in, sizeof(float) * SEQ * D_MODEL,
                    cudaMemcpyDeviceToDevice, 0);

    const dim3 blk(256);

    for (int l = 0; l < NLAYERS; l++) {
        const float* Wq = wq + (size_t)l * D_MODEL * D_MODEL;
        const float* Wk = wk + (size_t)l * D_MODEL * D_MODEL;
        const float* Wv = wv + (size_t)l * D_MODEL * D_MODEL;
        const float* Wo = wo + (size_t)l * D_MODEL * D_MODEL;
        const float* W1 = w1 + (size_t)l * D_MODEL * DFF;
        const float* W2 = w2 + (size_t)l * DFF * D_MODEL;

        // ---- pack weights (transposed, [N,3K], hi|hi|lo) ----
        pack_wT<<<dim3(D_MODEL/32, D_MODEL/32, 1), blk>>>(Wq, D_MODEL, 0, wqp, D_MODEL, 0);
        pack_wT<<<dim3(D_MODEL/32, D_MODEL/32, 1), blk>>>(Wk, D_MODEL, 0, wkp, D_MODEL, 0);
        pack_wT<<<dim3(D_MODEL/32, D_MODEL/32, 1), blk>>>(Wv, D_MODEL, 0, wvp, D_MODEL, 0);
        pack_wT<<<dim3(D_MODEL/32, D_MODEL/32, 1), blk>>>(Wo, D_MODEL, 0, wop, D_MODEL, 0);
        pack_wT<<<dim3(DFF/32,     D_MODEL/32, 1), blk>>>(W1, DFF,     0, w1p, D_MODEL, 0);
        pack_wT<<<dim3(D_MODEL/32, DFF/32,     1), blk>>>(W2, D_MODEL, 0, w2p, DFF,     0);

        // ---- QKV projections -> bf16 head-major (Q pre-scaled by 1/8) ----
        pack_act<<<dim3(D_MODEL/256, SEQ, 1), blk>>>(x, xp, D_MODEL, 0, 0);
        gemm_tc<128, 2><<<dim3(D_MODEL/128, SEQ/128, 1), blk>>>(
            xp, 3*D_MODEL, 0, wqp, 3*D_MODEL, 0, (float*)qb, 0, 0,
            bq + (size_t)l * D_MODEL, D_MODEL/32, D_MODEL, 0.125f);
        gemm_tc<128, 2><<<dim3(D_MODEL/128, SEQ/128, 1), blk>>>(
            xp, 3*D_MODEL, 0, wkp, 3*D_MODEL, 0, (float*)kb, 0, 0,
            bk + (size_t)l * D_MODEL, D_MODEL/32, D_MODEL, 1.0f);
        gemm_tc<128, 2><<<dim3(D_MODEL/128, SEQ/128, 1), blk>>>(
            xp, 3*D_MODEL, 0, wvp, 3*D_MODEL, 0, (float*)vb, 0, 0,
            bv + (size_t)l * D_MODEL, D_MODEL/32, D_MODEL, 1.0f);

        // ---- flash attention: ctx = softmax(Q K^T) V ----
        flash_attn<<<dim3(SEQ/128, NHEAD), blk, FLASH_SMEM>>>(qb, kb, vb, ctx);

        // ---- output projection + LN1 ----
        pack_act<<<dim3(D_MODEL/256, SEQ, 1), blk>>>(ctx, xp, D_MODEL, 0, 0);
        gemm_tc<128, 0><<<dim3(D_MODEL/128, SEQ/128, 1), blk>>>(
            xp, 3*D_MODEL, 0, wop, 3*D_MODEL, 0, t1, D_MODEL, 0,
            bo + (size_t)l * D_MODEL, D_MODEL/32, D_MODEL, 1.0f);
        add_ln_kernel<<<SEQ, blk>>>(x, t1,
            ln1g + (size_t)l * D_MODEL, ln1b + (size_t)l * D_MODEL);

        // ---- FFN ----
        pack_act<<<dim3(D_MODEL/256, SEQ, 1), blk>>>(x, xp, D_MODEL, 0, 0);
        gemm_tc<128, 1><<<dim3(DFF/128, SEQ/128, 1), blk>>>(
            xp, 3*D_MODEL, 0, w1p, 3*D_MODEL, 0, h, DFF, 0,
            b1 + (size_t)l * DFF, D_MODEL/32, D_MODEL, 1.0f);
        pack_act<<<dim3(DFF/256, SEQ, 1), blk>>>(h, hp, DFF, 0, 0);
        gemm_tc<128, 0><<<dim3(D_MODEL/128, SEQ/128, 1), blk>>>(
            hp, 3*DFF, 0, w2p, 3*DFF, 0, t1, D_MODEL, 0,
            b2 + (size_t)l * D_MODEL, DFF/32, DFF, 1.0f);
        add_ln_kernel<<<SEQ, blk>>>(x, t1,
            ln2g + (size_t)l * D_MODEL, ln2b + (size_t)l * D_MODEL);
    }

    cudaMemcpyAsync(d_out, x, sizeof(float) * SEQ * D_MODEL,
                    cudaMemcpyDeviceToDevice, 0);
}

// round 7
// speedup vs baseline: 2.4469x; 1.0250x over previous
#include <cuda_runtime.h>
#include <cuda_bf16.h>
#include <math.h>
#include <stdint.h>

#define D_MODEL 1024
#define SEQ     2048
#define NHEAD   16
#define DK      64
#define DFF     4096
#define NLAYERS 4

// ===================== scratch (static device globals) ======================
__device__ float g_x  [SEQ * D_MODEL];
__device__ float g_t1 [SEQ * D_MODEL];

// 2-segment split-bf16 operands: [hi(K) | lo(K)]
// A-side GEMM segment offsets {0, K, 0}; B-side {0, 0, K}
__device__ __nv_bfloat16 g_xp  [(size_t)SEQ * 2 * D_MODEL];      // activations
__device__ __nv_bfloat16 g_cp  [(size_t)SEQ * 2 * D_MODEL];      // packed ctx
__device__ __nv_bfloat16 g_hp  [(size_t)SEQ * 2 * DFF];          // packed FFN mid
__device__ __nv_bfloat16 g_wqkvp[(size_t)3 * D_MODEL * 2 * D_MODEL];
__device__ __nv_bfloat16 g_wop [(size_t)D_MODEL * 2 * D_MODEL];
__device__ __nv_bfloat16 g_w1p [(size_t)DFF * 2 * D_MODEL];
__device__ __nv_bfloat16 g_w2p [(size_t)D_MODEL * 2 * DFF];
__device__ float         g_bqkv[3 * D_MODEL];

// head-major bf16 q/k/v: [3][H][SEQ][DK] (q pre-scaled by 1/8)
__device__ __nv_bfloat16 g_qkvb[(size_t)3 * NHEAD * SEQ * DK];

// ===================== helpers =============================================
__device__ __forceinline__ uint32_t smem_to_u32(const void* p) {
    uint32_t a;
    asm("{ .reg .u64 t; cvta.to.shared.u64 t, %1; cvt.u32.u64 %0, t; }"
        : "=r"(a) : "l"(p));
    return a;
}

__device__ __forceinline__ float gelu_f(float x) {
    const float c = 0.7978845608028654f;
    float t = tanhf(c * (x + 0.044715f * x * x * x));
    return 0.5f * x * (1.0f + t);
}

#define CP_ASYNC16(dst, src) \
    asm volatile("cp.async.cg.shared.global [%0], [%1], 16;" \
        :: "r"(dst), "l"(src) : "memory")
#define CP_COMMIT() asm volatile("cp.async.commit_group;" ::: "memory")
#define CP_WAIT(N)  asm volatile("cp.async.wait_group %0;" :: "n"(N) : "memory")

#define LDMATRIX_X4(r0, r1, r2, r3, addr) \
    asm volatile("ldmatrix.sync.aligned.m8n8.x4.shared.b16 {%0,%1,%2,%3}, [%4];" \
        : "=r"(r0), "=r"(r1), "=r"(r2), "=r"(r3) : "r"(addr))

#define LDMATRIX_X4_T(r0, r1, r2, r3, addr) \
    asm volatile("ldmatrix.sync.aligned.m8n8.x4.trans.shared.b16 {%0,%1,%2,%3}, [%4];" \
        : "=r"(r0), "=r"(r1), "=r"(r2), "=r"(r3) : "r"(addr))

#define MMA_16816(c, a, b0, b1) \
    asm volatile("mma.sync.aligned.m16n8k16.row.col.f32.bf16.bf16.f32 " \
        "{%0,%1,%2,%3}, {%4,%5,%6,%7}, {%8,%9}, {%0,%1,%2,%3};" \
        : "+f"((c)[0]), "+f"((c)[1]), "+f"((c)[2]), "+f"((c)[3]) \
        : "r"((a)[0]), "r"((a)[1]), "r"((a)[2]), "r"((a)[3]), \
          "r"(b0), "r"(b1))

__device__ __forceinline__ void split_bf16(float v, __nv_bfloat16& hi,
                                           __nv_bfloat16& lo) {
    hi = __float2bfloat16_rn(v);
    lo = __float2bfloat16_rn(v - __bfloat162float(hi));
}

// ===================== HMMA split-bf16 GEMM =================================
// C tile [128, BN] = sum over 3 segments of A[m, aOff+k] * B[n, bOff+k]
// ACT: 0 = fp32 (acc*alpha + bias)
//      3 = GELU(acc + bias) -> packed bf16 [hi|lo], row stride 2*ldc
//      4 = QKV head-major bf16: (acc + bias)*sc, sc = col<1024 ? 0.125 : 1
#define SA 80   // padded smem row stride bytes (40 bf16) -> LDSM conflict-free

template <int BN, int ACT>
__global__ __launch_bounds__(256)
void gemm_tc(const __nv_bfloat16* __restrict__ A, int lda,
             const __nv_bfloat16* __restrict__ B, int ldb,
             float* __restrict__ C, int ldc,
             const float* __restrict__ bias, int segIters,
             int aO0, int aO1, int aO2, int bO0, int bO1, int bO2,
             float alpha)
{
    constexpr int WN    = BN / 2;
    constexpr int NG    = WN / 16;
    constexpr int ATILE = 128 * SA;
    constexpr int BTILE = BN * SA;
    __shared__ __align__(16) char sm[2 * ATILE + 2 * BTILE];

    const uint32_t smb = smem_to_u32(sm);
    const int tid  = threadIdx.x;
    const int wid  = tid >> 5;
    const int lane = tid & 31;

    const int bm = blockIdx.y * 128;
    const int bn = blockIdx.x * BN;
    const int wm = (wid & 3) * 32;
    const int wn = (wid >> 2) * WN;

    const int aOff[3] = {aO0, aO1, aO2};
    const int bOff[3] = {bO0, bO1, bO2};

    float acc[2][2 * NG][4];
#pragma unroll
    for (int i = 0; i < 2; i++)
#pragma unroll
        for (int j = 0; j < 2 * NG; j++)
#pragma unroll
            for (int r = 0; r < 4; r++) acc[i][j][r] = 0.0f;

    const int lr = tid >> 2;
    const int lq = tid & 3;
    const int nIter = 3 * segIters;

    auto load_tiles = [&](int it, int s) {
        const int seg = it / segIters;
        const int ko  = (it - seg * segIters) * 32;
        const int ka  = aOff[seg] + ko;
        const int kb  = bOff[seg] + ko;
        const uint32_t abuf = smb + s * ATILE;
        const uint32_t bbuf = smb + 2 * ATILE + s * BTILE;
#pragma unroll
        for (int rr = 0; rr < 128; rr += 64) {
            CP_ASYNC16(abuf + (lr + rr) * SA + lq * 16,
                       A + (size_t)(bm + lr + rr) * lda + ka + lq * 8);
        }
#pragma unroll
        for (int rr = 0; rr < BN; rr += 64) {
            CP_ASYNC16(bbuf + (lr + rr) * SA + lq * 16,
                       B + (size_t)(bn + lr + rr) * ldb + kb + lq * 8);
        }
        CP_COMMIT();
    };

    load_tiles(0, 0);

    for (int it = 0; it < nIter; ++it) {
        const int s = it & 1;
        if (it + 1 < nIter) { load_tiles(it + 1, s ^ 1); CP_WAIT(1); }
        else                { CP_WAIT(0); }
        __syncthreads();

        const uint32_t abuf = smb + s * ATILE;
        const uint32_t bbuf = smb + 2 * ATILE + s * BTILE;
        const int lrow = lane & 15;
        const int lcol = (lane >> 4) * 16;

#pragma unroll
        for (int kk = 0; kk < 2; ++kk) {
            uint32_t a[2][4];
#pragma unroll
            for (int mf = 0; mf < 2; ++mf) {
                LDMATRIX_X4(a[mf][0], a[mf][1], a[mf][2], a[mf][3],
                            abuf + (wm + mf * 16 + lrow) * SA + kk * 32 + lcol);
            }
#pragma unroll
            for (int g = 0; g < NG; ++g) {
                uint32_t b0, b1, b2, b3;
                LDMATRIX_X4(b0, b1, b2, b3,
                            bbuf + (wn + g * 16 + lrow) * SA + kk * 32 + lcol);
#pragma unroll
                for (int mf = 0; mf < 2; ++mf) {
                    MMA_16816(acc[mf][2 * g],     a[mf], b0, b2);
                    MMA_16816(acc[mf][2 * g + 1], a[mf], b1, b3);
                }
            }
        }
        __syncthreads();
    }

    // ---- epilogue ----
    const int tq = lane >> 2;
    const int tr = lane & 3;
#pragma unroll
    for (int mf = 0; mf < 2; ++mf) {
        const int row0 = bm + wm + mf * 16 + tq;
#pragma unroll
        for (int nf = 0; nf < 2 * NG; ++nf) {
            const int col = bn + wn + nf * 8 + tr * 2;
            float bx = 0.0f, by = 0.0f;
            if (bias) { bx = bias[col]; by = bias[col + 1]; }
#pragma unroll
            for (int hh = 0; hh < 2; ++hh) {
                const int row = row0 + hh * 8;
                float vx = acc[mf][nf][2 * hh];
                float vy = acc[mf][nf][2 * hh + 1];
                if (ACT == 0) {
                    *(float2*)(C + (size_t)row * ldc + col) =
                        make_float2(vx * alpha + bx, vy * alpha + by);
                } else if (ACT == 3) {
                    vx = gelu_f(vx + bx);
                    vy = gelu_f(vy + by);
                    __nv_bfloat16 hx, lx, hy, ly;
                    split_bf16(vx, hx, lx);
                    split_bf16(vy, hy, ly);
                    __nv_bfloat162 hp2 = __halves2bfloat162(hx, hy);
                    __nv_bfloat162 lp2 = __halves2bfloat162(lx, ly);
                    __nv_bfloat16* Cb = (__nv_bfloat16*)C;
                    const size_t base = (size_t)row * (2 * ldc) + col;
                    *(uint32_t*)&Cb[base]       = *(uint32_t*)&hp2;
                    *(uint32_t*)&Cb[base + ldc] = *(uint32_t*)&lp2;
                } else { // ACT == 4: QKV head-major
                    const float sc = (col < D_MODEL) ? 0.125f : 1.0f;
                    vx = (vx + bx) * sc;
                    vy = (vy + by) * sc;
                    __nv_bfloat162 p = __floats2bfloat162_rn(vx, vy);
                    __nv_bfloat16* Cb = (__nv_bfloat16*)C;
                    const int buf  = col >> 10;
                    const int hcol = col & (D_MODEL - 1);
                    const size_t idx =
                        (size_t)buf * NHEAD * SEQ * DK +
                        ((size_t)(hcol >> 6) * SEQ + row) * DK + (hcol & 63);
                    *(uint32_t*)&Cb[idx] = *(uint32_t*)&p;
                }
            }
        }
    }
}

// ===================== flash attention ======================================
// One CTA = (head, 128-query block). 8 warps, warp w owns rows [w*16, w*16+16).
// Output: packed split-bf16 ctx into g_cp [SEQ, 2*D_MODEL].
#define FSTR 144

__global__ __launch_bounds__(256, 1)
void flash_attn(const __nv_bfloat16* __restrict__ QKV,
                __nv_bfloat16* __restrict__ Cp)
{
    extern __shared__ __align__(16) char sm[];
    const uint32_t smb = smem_to_u32(sm);
    const uint32_t Qs  = smb;
    const uint32_t KsB = smb + 128 * FSTR;
    const uint32_t VsB = smb + 3 * 128 * FSTR;

    const int tid  = threadIdx.x;
    const int wid  = tid >> 5;
    const int lane = tid & 31;
    const int qb   = blockIdx.x;
    const int h    = blockIdx.y;

    const __nv_bfloat16* Qh = QKV + ((size_t)h * SEQ + qb * 128) * DK;
    const __nv_bfloat16* Kh = QKV + (size_t)NHEAD * SEQ * DK
                                  + (size_t)h * SEQ * DK;
    const __nv_bfloat16* Vh = QKV + (size_t)2 * NHEAD * SEQ * DK
                                  + (size_t)h * SEQ * DK;

    // ---- stage Q tile ----
#pragma unroll
    for (int i = 0; i < 4; i++) {
        const int idx = tid + i * 256;
        const int r = idx >> 3, c = idx & 7;
        *(float4*)(sm + r * FSTR + c * 16) =
            *(const float4*)(Qh + (size_t)r * DK + c * 8);
    }
    __syncthreads();

    const int lrow  = lane & 15;
    const int lcolb = (lane >> 4) * 16;
    uint32_t qf[4][4];
#pragma unroll
    for (int kc = 0; kc < 4; kc++)
        LDMATRIX_X4(qf[kc][0], qf[kc][1], qf[kc][2], qf[kc][3],
                    Qs + (wid * 16 + lrow) * FSTR + kc * 32 + lcolb);

    auto load_kv = [&](int kb, int s) {
        const uint32_t kd = KsB + s * 128 * FSTR;
        const uint32_t vd = VsB + s * 128 * FSTR;
#pragma unroll
        for (int i = 0; i < 4; i++) {
            const int idx = tid + i * 256;
            const int r = idx >> 3, c = idx & 7;
            CP_ASYNC16(kd + r * FSTR + c * 16,
                       Kh + (size_t)(kb * 128 + r) * DK + c * 8);
            CP_ASYNC16(vd + r * FSTR + c * 16,
                       Vh + (size_t)(kb * 128 + r) * DK + c * 8);
        }
        CP_COMMIT();
    };

    float m0 = -1e30f, m1 = -1e30f, l0 = 0.0f, l1 = 0.0f;
    float ctxa[8][4];
#pragma unroll
    for (int i = 0; i < 8; i++)
#pragma unroll
        for (int j = 0; j < 4; j++) ctxa[i][j] = 0.0f;

    load_kv(0, 0);

    for (int kb = 0; kb < SEQ / 128; ++kb) {
        const int s = kb & 1;
        if (kb + 1 < SEQ / 128) { load_kv(kb + 1, s ^ 1); CP_WAIT(1); }
        else                    { CP_WAIT(0); }
        __syncthreads();

        const uint32_t Ks = KsB + s * 128 * FSTR;
        const uint32_t Vs = VsB + s * 128 * FSTR;

        float sacc[16][4];
#pragma unroll
        for (int i = 0; i < 16; i++)
#pragma unroll
            for (int j = 0; j < 4; j++) sacc[i][j] = 0.0f;

#pragma unroll
        for (int kc = 0; kc < 4; kc++) {
#pragma unroll
            for (int ng = 0; ng < 8; ng++) {
                uint32_t b0, b1, b2, b3;
                LDMATRIX_X4(b0, b1, b2, b3,
                            Ks + (ng * 16 + lrow) * FSTR + kc * 32 + lcolb);
                MMA_16816(sacc[2 * ng],     qf[kc], b0, b2);
                MMA_16816(sacc[2 * ng + 1], qf[kc], b1, b3);
            }
        }

        float mn0 = -1e30f, mn1 = -1e30f;
#pragma unroll
        for (int f = 0; f < 16; f++) {
            mn0 = fmaxf(mn0, fmaxf(sacc[f][0], sacc[f][1]));
            mn1 = fmaxf(mn1, fmaxf(sacc[f][2], sacc[f][3]));
        }
        mn0 = fmaxf(mn0, __shfl_xor_sync(0xffffffffu, mn0, 1));
        mn0 = fmaxf(mn0, __shfl_xor_sync(0xffffffffu, mn0, 2));
        mn1 = fmaxf(mn1, __shfl_xor_sync(0xffffffffu, mn1, 1));
        mn1 = fmaxf(mn1, __shfl_xor_sync(0xffffffffu, mn1, 2));

        const float mN0 = fmaxf(m0, mn0);
        const float mN1 = fmaxf(m1, mn1);
        const float c0 = __expf(m0 - mN0);
        const float c1 = __expf(m1 - mN1);

        float rs0 = 0.0f, rs1 = 0.0f;
        uint32_t pl[16], ph[16];
#pragma unroll
        for (int f = 0; f < 16; f++) {
            const float e0 = __expf(sacc[f][0] - mN0);
            const float e1 = __expf(sacc[f][1] - mN0);
            const float e2 = __expf(sacc[f][2] - mN1);
            const float e3 = __expf(sacc[f][3] - mN1);
            rs0 += e0 + e1;
            rs1 += e2 + e3;
            __nv_bfloat162 t0 = __floats2bfloat162_rn(e0, e1);
            __nv_bfloat162 t1 = __floats2bfloat162_rn(e2, e3);
            pl[f] = *(uint32_t*)&t0;
            ph[f] = *(uint32_t*)&t1;
        }
        rs0 += __shfl_xor_sync(0xffffffffu, rs0, 1);
        rs0 += __shfl_xor_sync(0xffffffffu, rs0, 2);
        rs1 += __shfl_xor_sync(0xffffffffu, rs1, 1);
        rs1 += __shfl_xor_sync(0xffffffffu, rs1, 2);

        l0 = l0 * c0 + rs0;
        l1 = l1 * c1 + rs1;
        m0 = mN0;
        m1 = mN1;
#pragma unroll
        for (int nf = 0; nf < 8; nf++) {
            ctxa[nf][0] *= c0; ctxa[nf][1] *= c0;
            ctxa[nf][2] *= c1; ctxa[nf][3] *= c1;
        }

#pragma unroll
        for (int kc = 0; kc < 8; kc++) {
            uint32_t ap[4] = { pl[2 * kc], ph[2 * kc],
                               pl[2 * kc + 1], ph[2 * kc + 1] };
#pragma unroll
            for (int vg = 0; vg < 4; vg++) {
                uint32_t r0, r1, r2, r3;
                LDMATRIX_X4_T(r0, r1, r2, r3,
                              Vs + (kc * 16 + lrow) * FSTR + vg * 32 + lcolb);
                MMA_16816(ctxa[2 * vg],     ap, r0, r1);
                MMA_16816(ctxa[2 * vg + 1], ap, r2, r3);
            }
        }
        __syncthreads();
    }

    // ---- epilogue: packed split-bf16 ctx ----
    const float il0 = 1.0f / l0;
    const float il1 = 1.0f / l1;
    const int row0 = qb * 128 + wid * 16 + (lane >> 2);
    const int colb = h * DK + (lane & 3) * 2;
#pragma unroll
    for (int nf = 0; nf < 8; nf++) {
        const int col = colb + nf * 8;
#pragma unroll
        for (int hh = 0; hh < 2; hh++) {
            const int row = row0 + hh * 8;
            const float il = hh ? il1 : il0;
            const float vx = ctxa[nf][2 * hh]     * il;
            const float vy = ctxa[nf][2 * hh + 1] * il;
            __nv_bfloat16 hx, lx, hy, ly;
            split_bf16(vx, hx, lx);
            split_bf16(vy, hy, ly);
            __nv_bfloat162 h2 = __halves2bfloat162(hx, hy);
            __nv_bfloat162 l2 = __halves2bfloat162(lx, ly);
            const size_t base = (size_t)row * (2 * D_MODEL) + col;
            *(uint32_t*)&Cp[base]           = *(uint32_t*)&h2;
            *(uint32_t*)&Cp[base + D_MODEL] = *(uint32_t*)&l2;
        }
    }
}

// ===================== packing / misc kernels ===============================
// fp32 [M,K] -> bf16 [M,2K] packed [hi|lo]
__global__ __launch_bounds__(256)
void pack_x(const float* __restrict__ in, __nv_bfloat16* __restrict__ out,
            int K)
{
    const int k = blockIdx.x * 256 + threadIdx.x;
    const int r = blockIdx.y;
    const float v = in[(size_t)r * K + k];
    __nv_bfloat16 hi, lo;
    split_bf16(v, hi, lo);
    const size_t o = (size_t)r * 2 * K;
    out[o + k]     = hi;
    out[o + K + k] = lo;
}

// fp32 in[K,N] (ld=ldIn) -> bf16 out[N,2K] packed [hi|lo]
__global__ __launch_bounds__(256)
void pack_wT(const float* __restrict__ in, int ldIn,
             __nv_bfloat16* __restrict__ out, int K)
{
    __shared__ float t[32][33];
    const int k0 = blockIdx.y * 32;
    const int n0 = blockIdx.x * 32;
    const int tx = threadIdx.x & 31;
    const int ty = threadIdx.x >> 5;
#pragma unroll
    for (int i = 0; i < 32; i += 8)
        t[ty + i][tx] = in[(size_t)(k0 + ty + i) * ldIn + n0 + tx];
    __syncthreads();
#pragma unroll
    for (int i = 0; i < 32; i += 8) {
        const float v = t[tx][ty + i];
        __nv_bfloat16 hi, lo;
        split_bf16(v, hi, lo);
        const size_t o = (size_t)(n0 + ty + i) * 2 * K;
        out[o + k0 + tx]     = hi;
        out[o + K + k0 + tx] = lo;
    }
}

__global__ __launch_bounds__(256)
void concat_bias(const float* __restrict__ bq, const float* __restrict__ bk,
                 const float* __restrict__ bv, float* __restrict__ out)
{
    const int i = blockIdx.x * 256 + threadIdx.x;
    float v;
    if (i < D_MODEL)            v = bq[i];
    else if (i < 2 * D_MODEL)   v = bk[i - D_MODEL];
    else                        v = bv[i - 2 * D_MODEL];
    out[i] = v;
}

// ===================== fused residual add + LayerNorm + pack ================
__global__ __launch_bounds__(256) void add_ln_kernel(
    float* __restrict__ x, const float* __restrict__ res,
    const float* __restrict__ g, const float* __restrict__ b,
    __nv_bfloat16* __restrict__ xp)
{
    __shared__ float red[8];
    const size_t base = (size_t)blockIdx.x * D_MODEL;
    const int tid = threadIdx.x;
    const int lane = tid & 31, wid = tid >> 5;

    float4 xv = *(const float4*)&x[base + tid * 4];
    float4 rv = *(const float4*)&res[base + tid * 4];
    float v0 = xv.x + rv.x, v1 = xv.y + rv.y, v2 = xv.z + rv.z, v3 = xv.w + rv.w;

    float s = v0 + v1 + v2 + v3;
#pragma unroll
    for (int o = 16; o > 0; o >>= 1) s += __shfl_xor_sync(0xffffffffu, s, o);
    if (lane == 0) red[wid] = s;
    __syncthreads();
    float tot = 0.0f;
#pragma unroll
    for (int i = 0; i < 8; i++) tot += red[i];
    const float mu = tot * (1.0f / D_MODEL);
    __syncthreads();

    float d0 = v0 - mu, d1 = v1 - mu, d2 = v2 - mu, d3 = v3 - mu;
    float s2 = d0 * d0 + d1 * d1 + d2 * d2 + d3 * d3;
#pragma unroll
    for (int o = 16; o > 0; o >>= 1) s2 += __shfl_xor_sync(0xffffffffu, s2, o);
    if (lane == 0) red[wid] = s2;
    __syncthreads();
    float tot2 = 0.0f;
#pragma unroll
    for (int i = 0; i < 8; i++) tot2 += red[i];
    const float rs = rsqrtf(tot2 * (1.0f / D_MODEL) + 1e-5f);

    const int c = tid * 4;
    float4 gg = *(const float4*)&g[c];
    float4 bb = *(const float4*)&b[c];
    float4 out;
    out.x = d0 * rs * gg.x + bb.x;
    out.y = d1 * rs * gg.y + bb.y;
    out.z = d2 * rs * gg.z + bb.z;
    out.w = d3 * rs * gg.w + bb.w;
    *(float4*)&x[base + c] = out;

    // packed split-bf16 emit
    __nv_bfloat16 h0, l0_, h1, l1_, h2, l2_, h3, l3_;
    split_bf16(out.x, h0, l0_);
    split_bf16(out.y, h1, l1_);
    split_bf16(out.z, h2, l2_);
    split_bf16(out.w, h3, l3_);
    __nv_bfloat162 hA = __halves2bfloat162(h0, h1);
    __nv_bfloat162 hB = __halves2bfloat162(h2, h3);
    __nv_bfloat162 lA = __halves2bfloat162(l0_, l1_);
    __nv_bfloat162 lB = __halves2bfloat162(l2_, l3_);
    const size_t pb = (size_t)blockIdx.x * 2 * D_MODEL + c;
    *(uint32_t*)&xp[pb]               = *(uint32_t*)&hA;
    *(uint32_t*)&xp[pb + 2]           = *(uint32_t*)&hB;
    *(uint32_t*)&xp[pb + D_MODEL]     = *(uint32_t*)&lA;
    *(uint32_t*)&xp[pb + D_MODEL + 2] = *(uint32_t*)&lB;
}

// ===================== host =================================================
extern "C" void kernel_launch(void* const* d_in, const int* in_sizes, int n_in,
                              void* d_out, int out_size)
{
    const float* x_in = (const float*)d_in[0];
    const float* wq = (const float*)d_in[1];
    const float* bq = (const float*)d_in[2];
    const float* wk = (const float*)d_in[3];
    const float* bk = (const float*)d_in[4];
    const float* wv = (const float*)d_in[5];
    const float* bv = (const float*)d_in[6];
    const float* wo = (const float*)d_in[7];
    const float* bo = (const float*)d_in[8];
    const float* w1 = (const float*)d_in[9];
    const float* b1 = (const float*)d_in[10];
    const float* w2 = (const float*)d_in[11];
    const float* b2 = (const float*)d_in[12];
    const float* ln1g = (const float*)d_in[13];
    const float* ln1b = (const float*)d_in[14];
    const float* ln2g = (const float*)d_in[15];
    const float* ln2b = (const float*)d_in[16];

    float *x, *t1, *bqkv;
    __nv_bfloat16 *xp, *cp, *hp, *wqkvp, *wop, *w1p, *w2p, *qkvb;
    cudaGetSymbolAddress((void**)&x,     g_x);
    cudaGetSymbolAddress((void**)&t1,    g_t1);
    cudaGetSymbolAddress((void**)&bqkv,  g_bqkv);
    cudaGetSymbolAddress((void**)&xp,    g_xp);
    cudaGetSymbolAddress((void**)&cp,    g_cp);
    cudaGetSymbolAddress((void**)&hp,    g_hp);
    cudaGetSymbolAddress((void**)&wqkvp, g_wqkvp);
    cudaGetSymbolAddress((void**)&wop,   g_wop);
    cudaGetSymbolAddress((void**)&w1p,   g_w1p);
    cudaGetSymbolAddress((void**)&w2p,   g_w2p);
    cudaGetSymbolAddress((void**)&qkvb,  g_qkvb);

    const int FLASH_SMEM = 5 * 128 * FSTR;
    cudaFuncSetAttribute(flash_attn,
        cudaFuncAttributeMaxDynamicSharedMemorySize, FLASH_SMEM);

    cudaMemcpyAsync(x, x_in, sizeof(float) * SEQ * D_MODEL,
                    cudaMemcpyDeviceToDevice, 0);

    const dim3 blk(256);

    // initial pack of x (layer 0 QKV input); later layers get xp from add_ln
    pack_x<<<dim3(D_MODEL/256, SEQ), blk>>>(x, xp, D_MODEL);

    for (int l = 0; l < NLAYERS; l++) {
        const float* Wq = wq + (size_t)l * D_MODEL * D_MODEL;
        const float* Wk = wk + (size_t)l * D_MODEL * D_MODEL;
        const float* Wv = wv + (size_t)l * D_MODEL * D_MODEL;
        const float* Wo = wo + (size_t)l * D_MODEL * D_MODEL;
        const float* W1 = w1 + (size_t)l * D_MODEL * DFF;
        const float* W2 = w2 + (size_t)l * DFF * D_MODEL;

        // ---- pack weights ([N, 2K] hi|lo) ----
        pack_wT<<<dim3(D_MODEL/32, D_MODEL/32), blk>>>(Wq, D_MODEL, wqkvp, D_MODEL);
        pack_wT<<<dim3(D_MODEL/32, D_MODEL/32), blk>>>(Wk, D_MODEL,
            wqkvp + (size_t)D_MODEL * 2 * D_MODEL, D_MODEL);
        pack_wT<<<dim3(D_MODEL/32, D_MODEL/32), blk>>>(Wv, D_MODEL,
            wqkvp + (size_t)2 * D_MODEL * 2 * D_MODEL, D_MODEL);
        pack_wT<<<dim3(D_MODEL/32, D_MODEL/32), blk>>>(Wo, D_MODEL, wop, D_MODEL);
        pack_wT<<<dim3(DFF/32,     D_MODEL/32), blk>>>(W1, DFF,     w1p, D_MODEL);
        pack_wT<<<dim3(D_MODEL/32, DFF/32),     blk>>>(W2, D_MODEL, w2p, DFF);
        concat_bias<<<dim3(3 * D_MODEL / 256), blk>>>(
            bq + (size_t)l * D_MODEL, bk + (size_t)l * D_MODEL,
            bv + (size_t)l * D_MODEL, bqkv);

        // ---- fused QKV projection -> head-major bf16 ----
        gemm_tc<128, 4><<<dim3(3 * D_MODEL / 128, SEQ / 128), blk>>>(
            xp, 2 * D_MODEL, wqkvp, 2 * D_MODEL, (float*)qkvb, 0,
            bqkv, D_MODEL / 32,
            0, D_MODEL, 0, 0, 0, D_MODEL, 1.0f);

        // ---- flash attention -> packed ctx ----
        flash_attn<<<dim3(SEQ / 128, NHEAD), blk, FLASH_SMEM>>>(qkvb, cp);

        // ---- output projection + LN1 (emits x + xp) ----
        gemm_tc<128, 0><<<dim3(D_MODEL / 128, SEQ / 128), blk>>>(
            cp, 2 * D_MODEL, wop, 2 * D_MODEL, t1, D_MODEL,
            bo + (size_t)l * D_MODEL, D_MODEL / 32,
            0, D_MODEL, 0, 0, 0, D_MODEL, 1.0f);
        add_ln_kernel<<<SEQ, blk>>>(x, t1,
            ln1g + (size_t)l * D_MODEL, ln1b + (size_t)l * D_MODEL, xp);

        // ---- FFN ----
        gemm_tc<128, 3><<<dim3(DFF / 128, SEQ / 128), blk>>>(
            xp, 2 * D_MODEL, w1p, 2 * D_MODEL, (float*)hp, DFF,
            b1 + (size_t)l * DFF, D_MODEL / 32,
            0, D_MODEL, 0, 0, 0, D_MODEL, 1.0f);
        gemm_tc<128, 0><<<dim3(D_MODEL / 128, SEQ / 128), blk>>>(
            hp, 2 * DFF, w2p, 2 * DFF, t1, D_MODEL,
            b2 + (size_t)l * D_MODEL, DFF / 32,
            0, DFF, 0, 0, 0, DFF, 1.0f);
        add_ln_kernel<<<SEQ, blk>>>(x, t1,
            ln2g + (size_t)l * D_MODEL, ln2b + (size_t)l * D_MODEL, xp);
    }

    cudaMemcpyAsync(d_out, x, sizeof(float) * SEQ * D_MODEL,
                    cudaMemcpyDeviceToDevice, 0);
}

// round 10
// speedup vs baseline: 4.0709x; 1.6637x over previous
#include <cuda_runtime.h>
#include <cuda_fp16.h>
#include <math.h>
#include <stdint.h>

#define D_MODEL 1024
#define SEQ     2048
#define NHEAD   16
#define DK      64
#define DFF     4096
#define NLAYERS 4

// ===================== scratch (static device globals) ======================
__device__ float g_x  [SEQ * D_MODEL];
__device__ float g_t1 [SEQ * D_MODEL];

// fp16 operands. Activation packs are 2-segment [hi(K) | lo(K)];
// weights are single-segment fp16 (their rounding is the accepted error).
__device__ __half g_xp  [(size_t)SEQ * 2 * D_MODEL];
__device__ __half g_cp  [(size_t)SEQ * D_MODEL];          // ctx (hi only)
__device__ __half g_hp  [(size_t)SEQ * 2 * DFF];          // FFN mid [hi|lo]
__device__ __half g_wqkvp[(size_t)3 * D_MODEL * D_MODEL];
__device__ __half g_wop [(size_t)D_MODEL * D_MODEL];
__device__ __half g_w1p [(size_t)DFF * D_MODEL];
__device__ __half g_w2p [(size_t)D_MODEL * DFF];
__device__ float  g_bqkv[3 * D_MODEL];

// head-major fp16 q/k/v: [3][H][SEQ][DK] (q pre-scaled by 1/8)
__device__ __half g_qkvb[(size_t)3 * NHEAD * SEQ * DK];

// ===================== helpers =============================================
__device__ __forceinline__ uint32_t smem_to_u32(const void* p) {
    uint32_t a;
    asm("{ .reg .u64 t; cvta.to.shared.u64 t, %1; cvt.u32.u64 %0, t; }"
        : "=r"(a) : "l"(p));
    return a;
}

__device__ __forceinline__ float gelu_f(float x) {
    const float c = 0.7978845608028654f;
    float t = tanhf(c * (x + 0.044715f * x * x * x));
    return 0.5f * x * (1.0f + t);
}

#define CP_ASYNC16(dst, src) \
    asm volatile("cp.async.cg.shared.global [%0], [%1], 16;" \
        :: "r"(dst), "l"(src) : "memory")
#define CP_COMMIT() asm volatile("cp.async.commit_group;" ::: "memory")
#define CP_WAIT(N)  asm volatile("cp.async.wait_group %0;" :: "n"(N) : "memory")

#define LDMATRIX_X4(r0, r1, r2, r3, addr) \
    asm volatile("ldmatrix.sync.aligned.m8n8.x4.shared.b16 {%0,%1,%2,%3}, [%4];" \
        : "=r"(r0), "=r"(r1), "=r"(r2), "=r"(r3) : "r"(addr))

#define LDMATRIX_X4_T(r0, r1, r2, r3, addr) \
    asm volatile("ldmatrix.sync.aligned.m8n8.x4.trans.shared.b16 {%0,%1,%2,%3}, [%4];" \
        : "=r"(r0), "=r"(r1), "=r"(r2), "=r"(r3) : "r"(addr))

#define MMA_16816(c, a, b0, b1) \
    asm volatile("mma.sync.aligned.m16n8k16.row.col.f32.f16.f16.f32 " \
        "{%0,%1,%2,%3}, {%4,%5,%6,%7}, {%8,%9}, {%0,%1,%2,%3};" \
        : "+f"((c)[0]), "+f"((c)[1]), "+f"((c)[2]), "+f"((c)[3]) \
        : "r"((a)[0]), "r"((a)[1]), "r"((a)[2]), "r"((a)[3]), \
          "r"(b0), "r"(b1))

__device__ __forceinline__ void split_f16(float v, __half& hi, __half& lo) {
    hi = __float2half_rn(v);
    lo = __float2half_rn(v - __half2float(hi));
}

// ===================== HMMA fp16 GEMM =======================================
// C tile [128, BN] = sum over nSegs segments of A[m, s*aSegStride+k] * B[n, k]
// ACT: 0 = fp32 (acc*alpha + bias)
//      3 = GELU(acc + bias) -> packed fp16 [hi|lo], row stride 2*ldc
//      4 = QKV head-major fp16: (acc + bias)*sc, sc = col<1024 ? 0.125 : 1
#define SA 80   // padded smem row stride bytes (40 fp16) -> LDSM conflict-free

template <int BN, int ACT>
__global__ __launch_bounds__(256)
void gemm_tc(const __half* __restrict__ A, int lda,
             const __half* __restrict__ B, int ldb,
             float* __restrict__ C, int ldc,
             const float* __restrict__ bias, int segIters, int nSegs,
             int aSegStride, float alpha)
{
    constexpr int WN    = BN / 2;
    constexpr int NG    = WN / 16;
    constexpr int ATILE = 128 * SA;
    constexpr int BTILE = BN * SA;
    __shared__ __align__(16) char sm[2 * ATILE + 2 * BTILE];

    const uint32_t smb = smem_to_u32(sm);
    const int tid  = threadIdx.x;
    const int wid  = tid >> 5;
    const int lane = tid & 31;

    const int bm = blockIdx.y * 128;
    const int bn = blockIdx.x * BN;
    const int wm = (wid & 3) * 32;
    const int wn = (wid >> 2) * WN;

    float acc[2][2 * NG][4];
#pragma unroll
    for (int i = 0; i < 2; i++)
#pragma unroll
        for (int j = 0; j < 2 * NG; j++)
#pragma unroll
            for (int r = 0; r < 4; r++) acc[i][j][r] = 0.0f;

    const int lr = tid >> 2;
    const int lq = tid & 3;
    const int nIter = nSegs * segIters;

    auto load_tiles = [&](int it, int s) {
        const int seg = it / segIters;
        const int ko  = (it - seg * segIters) * 32;
        const int ka  = seg * aSegStride + ko;
        const uint32_t abuf = smb + s * ATILE;
        const uint32_t bbuf = smb + 2 * ATILE + s * BTILE;
#pragma unroll
        for (int rr = 0; rr < 128; rr += 64) {
            CP_ASYNC16(abuf + (lr + rr) * SA + lq * 16,
                       A + (size_t)(bm + lr + rr) * lda + ka + lq * 8);
        }
#pragma unroll
        for (int rr = 0; rr < BN; rr += 64) {
            CP_ASYNC16(bbuf + (lr + rr) * SA + lq * 16,
                       B + (size_t)(bn + lr + rr) * ldb + ko + lq * 8);
        }
        CP_COMMIT();
    };

    load_tiles(0, 0);

    for (int it = 0; it < nIter; ++it) {
        const int s = it & 1;
        if (it + 1 < nIter) { load_tiles(it + 1, s ^ 1); CP_WAIT(1); }
        else                { CP_WAIT(0); }
        __syncthreads();

        const uint32_t abuf = smb + s * ATILE;
        const uint32_t bbuf = smb + 2 * ATILE + s * BTILE;
        const int lrow = lane & 15;
        const int lcol = (lane >> 4) * 16;

#pragma unroll
        for (int kk = 0; kk < 2; ++kk) {
            uint32_t a[2][4];
#pragma unroll
            for (int mf = 0; mf < 2; ++mf) {
                LDMATRIX_X4(a[mf][0], a[mf][1], a[mf][2], a[mf][3],
                            abuf + (wm + mf * 16 + lrow) * SA + kk * 32 + lcol);
            }
#pragma unroll
            for (int g = 0; g < NG; ++g) {
                uint32_t b0, b1, b2, b3;
                LDMATRIX_X4(b0, b1, b2, b3,
                            bbuf + (wn + g * 16 + lrow) * SA + kk * 32 + lcol);
#pragma unroll
                for (int mf = 0; mf < 2; ++mf) {
                    MMA_16816(acc[mf][2 * g],     a[mf], b0, b2);
                    MMA_16816(acc[mf][2 * g + 1], a[mf], b1, b3);
                }
            }
        }
        __syncthreads();
    }

    // ---- epilogue ----
    const int tq = lane >> 2;
    const int tr = lane & 3;
#pragma unroll
    for (int mf = 0; mf < 2; ++mf) {
        const int row0 = bm + wm + mf * 16 + tq;
#pragma unroll
        for (int nf = 0; nf < 2 * NG; ++nf) {
            const int col = bn + wn + nf * 8 + tr * 2;
            float bx = 0.0f, by = 0.0f;
            if (bias) { bx = bias[col]; by = bias[col + 1]; }
#pragma unroll
            for (int hh = 0; hh < 2; ++hh) {
                const int row = row0 + hh * 8;
                float vx = acc[mf][nf][2 * hh];
                float vy = acc[mf][nf][2 * hh + 1];
                if (ACT == 0) {
                    *(float2*)(C + (size_t)row * ldc + col) =
                        make_float2(vx * alpha + bx, vy * alpha + by);
                } else if (ACT == 3) {
                    vx = gelu_f(vx + bx);
                    vy = gelu_f(vy + by);
                    __half hx, lx, hy, ly;
                    split_f16(vx, hx, lx);
                    split_f16(vy, hy, ly);
                    __half2 hp2 = __halves2half2(hx, hy);
                    __half2 lp2 = __halves2half2(lx, ly);
                    __half* Cb = (__half*)C;
                    const size_t base = (size_t)row * (2 * ldc) + col;
                    *(uint32_t*)&Cb[base]       = *(uint32_t*)&hp2;
                    *(uint32_t*)&Cb[base + ldc] = *(uint32_t*)&lp2;
                } else { // ACT == 4: QKV head-major
                    const float sc = (col < D_MODEL) ? 0.125f : 1.0f;
                    vx = (vx + bx) * sc;
                    vy = (vy + by) * sc;
                    __half2 p = __floats2half2_rn(vx, vy);
                    __half* Cb = (__half*)C;
                    const int buf  = col >> 10;
                    const int hcol = col & (D_MODEL - 1);
                    const size_t idx =
                        (size_t)buf * NHEAD * SEQ * DK +
                        ((size_t)(hcol >> 6) * SEQ + row) * DK + (hcol & 63);
                    *(uint32_t*)&Cb[idx] = *(uint32_t*)&p;
                }
            }
        }
    }
}

// ===================== flash attention (fp16) ===============================
// One CTA = (head, 128-query block). 8 warps, warp w owns rows [w*16, w*16+16).
// Output: fp16 ctx (hi only) into g_cp [SEQ, D_MODEL].
#define FSTR 144

__global__ __launch_bounds__(256, 1)
void flash_attn(const __half* __restrict__ QKV,
                __half* __restrict__ Cp)
{
    extern __shared__ __align__(16) char sm[];
    const uint32_t smb = smem_to_u32(sm);
    const uint32_t Qs  = smb;
    const uint32_t KsB = smb + 128 * FSTR;
    const uint32_t VsB = smb + 3 * 128 * FSTR;

    const int tid  = threadIdx.x;
    const int wid  = tid >> 5;
    const int lane = tid & 31;
    const int qb   = blockIdx.x;
    const int h    = blockIdx.y;

    const __half* Qh = QKV + ((size_t)h * SEQ + qb * 128) * DK;
    const __half* Kh = QKV + (size_t)NHEAD * SEQ * DK + (size_t)h * SEQ * DK;
    const __half* Vh = QKV + (size_t)2 * NHEAD * SEQ * DK + (size_t)h * SEQ * DK;

    // ---- stage Q tile ----
#pragma unroll
    for (int i = 0; i < 4; i++) {
        const int idx = tid + i * 256;
        const int r = idx >> 3, c = idx & 7;
        *(float4*)(sm + r * FSTR + c * 16) =
            *(const float4*)(Qh + (size_t)r * DK + c * 8);
    }
    __syncthreads();

    const int lrow  = lane & 15;
    const int lcolb = (lane >> 4) * 16;
    uint32_t qf[4][4];
#pragma unroll
    for (int kc = 0; kc < 4; kc++)
        LDMATRIX_X4(qf[kc][0], qf[kc][1], qf[kc][2], qf[kc][3],
                    Qs + (wid * 16 + lrow) * FSTR + kc * 32 + lcolb);

    auto load_kv = [&](int kb, int s) {
        const uint32_t kd = KsB + s * 128 * FSTR;
        const uint32_t vd = VsB + s * 128 * FSTR;
#pragma unroll
        for (int i = 0; i < 4; i++) {
            const int idx = tid + i * 256;
            const int r = idx >> 3, c = idx & 7;
            CP_ASYNC16(kd + r * FSTR + c * 16,
                       Kh + (size_t)(kb * 128 + r) * DK + c * 8);
            CP_ASYNC16(vd + r * FSTR + c * 16,
                       Vh + (size_t)(kb * 128 + r) * DK + c * 8);
        }
        CP_COMMIT();
    };

    float m0 = -1e30f, m1 = -1e30f, l0 = 0.0f, l1 = 0.0f;
    float ctxa[8][4];
#pragma unroll
    for (int i = 0; i < 8; i++)
#pragma unroll
        for (int j = 0; j < 4; j++) ctxa[i][j] = 0.0f;

    load_kv(0, 0);

    for (int kb = 0; kb < SEQ / 128; ++kb) {
        const int s = kb & 1;
        if (kb + 1 < SEQ / 128) { load_kv(kb + 1, s ^ 1); CP_WAIT(1); }
        else                    { CP_WAIT(0); }
        __syncthreads();

        const uint32_t Ks = KsB + s * 128 * FSTR;
        const uint32_t Vs = VsB + s * 128 * FSTR;

        float sacc[16][4];
#pragma unroll
        for (int i = 0; i < 16; i++)
#pragma unroll
            for (int j = 0; j < 4; j++) sacc[i][j] = 0.0f;

#pragma unroll
        for (int kc = 0; kc < 4; kc++) {
#pragma unroll
            for (int ng = 0; ng < 8; ng++) {
                uint32_t b0, b1, b2, b3;
                LDMATRIX_X4(b0, b1, b2, b3,
                            Ks + (ng * 16 + lrow) * FSTR + kc * 32 + lcolb);
                MMA_16816(sacc[2 * ng],     qf[kc], b0, b2);
                MMA_16816(sacc[2 * ng + 1], qf[kc], b1, b3);
            }
        }

        float mn0 = -1e30f, mn1 = -1e30f;
#pragma unroll
        for (int f = 0; f < 16; f++) {
            mn0 = fmaxf(mn0, fmaxf(sacc[f][0], sacc[f][1]));
            mn1 = fmaxf(mn1, fmaxf(sacc[f][2], sacc[f][3]));
        }
        mn0 = fmaxf(mn0, __shfl_xor_sync(0xffffffffu, mn0, 1));
        mn0 = fmaxf(mn0, __shfl_xor_sync(0xffffffffu, mn0, 2));
        mn1 = fmaxf(mn1, __shfl_xor_sync(0xffffffffu, mn1, 1));
        mn1 = fmaxf(mn1, __shfl_xor_sync(0xffffffffu, mn1, 2));

        const float mN0 = fmaxf(m0, mn0);
        const float mN1 = fmaxf(m1, mn1);
        const float c0 = __expf(m0 - mN0);
        const float c1 = __expf(m1 - mN1);

        float rs0 = 0.0f, rs1 = 0.0f;
        uint32_t pl[16], ph[16];
#pragma unroll
        for (int f = 0; f < 16; f++) {
            const float e0 = __expf(sacc[f][0] - mN0);
            const float e1 = __expf(sacc[f][1] - mN0);
            const float e2 = __expf(sacc[f][2] - mN1);
            const float e3 = __expf(sacc[f][3] - mN1);
            rs0 += e0 + e1;
            rs1 += e2 + e3;
            __half2 t0 = __floats2half2_rn(e0, e1);
            __half2 t1 = __floats2half2_rn(e2, e3);
            pl[f] = *(uint32_t*)&t0;
            ph[f] = *(uint32_t*)&t1;
        }
        rs0 += __shfl_xor_sync(0xffffffffu, rs0, 1);
        rs0 += __shfl_xor_sync(0xffffffffu, rs0, 2);
        rs1 += __shfl_xor_sync(0xffffffffu, rs1, 1);
        rs1 += __shfl_xor_sync(0xffffffffu, rs1, 2);

        l0 = l0 * c0 + rs0;
        l1 = l1 * c1 + rs1;
        m0 = mN0;
        m1 = mN1;
#pragma unroll
        for (int nf = 0; nf < 8; nf++) {
            ctxa[nf][0] *= c0; ctxa[nf][1] *= c0;
            ctxa[nf][2] *= c1; ctxa[nf][3] *= c1;
        }

#pragma unroll
        for (int kc = 0; kc < 8; kc++) {
            uint32_t ap[4] = { pl[2 * kc], ph[2 * kc],
                               pl[2 * kc + 1], ph[2 * kc + 1] };
#pragma unroll
            for (int vg = 0; vg < 4; vg++) {
                uint32_t r0, r1, r2, r3;
                LDMATRIX_X4_T(r0, r1, r2, r3,
                              Vs + (kc * 16 + lrow) * FSTR + vg * 32 + lcolb);
                MMA_16816(ctxa[2 * vg],     ap, r0, r1);
                MMA_16816(ctxa[2 * vg + 1], ap, r2, r3);
            }
        }
        __syncthreads();
    }

    // ---- epilogue: fp16 ctx (hi only) ----
    const float il0 = 1.0f / l0;
    const float il1 = 1.0f / l1;
    const int row0 = qb * 128 + wid * 16 + (lane >> 2);
    const int colb = h * DK + (lane & 3) * 2;
#pragma unroll
    for (int nf = 0; nf < 8; nf++) {
        const int col = colb + nf * 8;
#pragma unroll
        for (int hh = 0; hh < 2; hh++) {
            const int row = row0 + hh * 8;
            const float il = hh ? il1 : il0;
            __half2 h2 = __floats2half2_rn(ctxa[nf][2 * hh] * il,
                                           ctxa[nf][2 * hh + 1] * il);
            *(uint32_t*)&Cp[(size_t)row * D_MODEL + col] = *(uint32_t*)&h2;
        }
    }
}

// ===================== packing / misc kernels ===============================
// fp32 [M,K] -> fp16 [M,2K] packed [hi|lo]
__global__ __launch_bounds__(256)
void pack_x(const float* __restrict__ in, __half* __restrict__ out, int K)
{
    const int k = blockIdx.x * 256 + threadIdx.x;
    const int r = blockIdx.y;
    const float v = in[(size_t)r * K + k];
    __half hi, lo;
    split_f16(v, hi, lo);
    const size_t o = (size_t)r * 2 * K;
    out[o + k]     = hi;
    out[o + K + k] = lo;
}

// fp32 in[K,N] (ld=ldIn) -> fp16 out[N,K] (single segment)
__global__ __launch_bounds__(256)
void pack_wT(const float* __restrict__ in, int ldIn,
             __half* __restrict__ out, int K)
{
    __shared__ float t[32][33];
    const int k0 = blockIdx.y * 32;
    const int n0 = blockIdx.x * 32;
    const int tx = threadIdx.x & 31;
    const int ty = threadIdx.x >> 5;
#pragma unroll
    for (int i = 0; i < 32; i += 8)
        t[ty + i][tx] = in[(size_t)(k0 + ty + i) * ldIn + n0 + tx];
    __syncthreads();
#pragma unroll
    for (int i = 0; i < 32; i += 8) {
        out[(size_t)(n0 + ty + i) * K + k0 + tx] =
            __float2half_rn(t[tx][ty + i]);
    }
}

__global__ __launch_bounds__(256)
void concat_bias(const float* __restrict__ bq, const float* __restrict__ bk,
                 const float* __restrict__ bv, float* __restrict__ out)
{
    const int i = blockIdx.x * 256 + threadIdx.x;
    float v;
    if (i < D_MODEL)            v = bq[i];
    else if (i < 2 * D_MODEL)   v = bk[i - D_MODEL];
    else                        v = bv[i - 2 * D_MODEL];
    out[i] = v;
}

// ===================== fused residual add + LayerNorm + pack ================
__global__ __launch_bounds__(256) void add_ln_kernel(
    float* __restrict__ x, const float* __restrict__ res,
    const float* __restrict__ g, const float* __restrict__ b,
    __half* __restrict__ xp)
{
    __shared__ float red[8];
    const size_t base = (size_t)blockIdx.x * D_MODEL;
    const int tid = threadIdx.x;
    const int lane = tid & 31, wid = tid >> 5;

    float4 xv = *(const float4*)&x[base + tid * 4];
    float4 rv = *(const float4*)&res[base + tid * 4];
    float v0 = xv.x + rv.x, v1 = xv.y + rv.y, v2 = xv.z + rv.z, v3 = xv.w + rv.w;

    float s = v0 + v1 + v2 + v3;
#pragma unroll
    for (int o = 16; o > 0; o >>= 1) s += __shfl_xor_sync(0xffffffffu, s, o);
    if (lane == 0) red[wid] = s;
    __syncthreads();
    float tot = 0.0f;
#pragma unroll
    for (int i = 0; i < 8; i++) tot += red[i];
    const float mu = tot * (1.0f / D_MODEL);
    __syncthreads();

    float d0 = v0 - mu, d1 = v1 - mu, d2 = v2 - mu, d3 = v3 - mu;
    float s2 = d0 * d0 + d1 * d1 + d2 * d2 + d3 * d3;
#pragma unroll
    for (int o = 16; o > 0; o >>= 1) s2 += __shfl_xor_sync(0xffffffffu, s2, o);
    if (lane == 0) red[wid] = s2;
    __syncthreads();
    float tot2 = 0.0f;
#pragma unroll
    for (int i = 0; i < 8; i++) tot2 += red[i];
    const float rs = rsqrtf(tot2 * (1.0f / D_MODEL) + 1e-5f);

    const int c = tid * 4;
    float4 gg = *(const float4*)&g[c];
    float4 bb = *(const float4*)&b[c];
    float4 out;
    out.x = d0 * rs * gg.x + bb.x;
    out.y = d1 * rs * gg.y + bb.y;
    out.z = d2 * rs * gg.z + bb.z;
    out.w = d3 * rs * gg.w + bb.w;
    *(float4*)&x[base + c] = out;

    __half h0, l0_, h1, l1_, h2, l2_, h3, l3_;
    split_f16(out.x, h0, l0_);
    split_f16(out.y, h1, l1_);
    split_f16(out.z, h2, l2_);
    split_f16(out.w, h3, l3_);
    __half2 hA = __halves2half2(h0, h1);
    __half2 hB = __halves2half2(h2, h3);
    __half2 lA = __halves2half2(l0_, l1_);
    __half2 lB = __halves2half2(l2_, l3_);
    const size_t pb = (size_t)blockIdx.x * 2 * D_MODEL + c;
    *(uint32_t*)&xp[pb]               = *(uint32_t*)&hA;
    *(uint32_t*)&xp[pb + 2]           = *(uint32_t*)&hB;
    *(uint32_t*)&xp[pb + D_MODEL]     = *(uint32_t*)&lA;
    *(uint32_t*)&xp[pb + D_MODEL + 2] = *(uint32_t*)&lB;
}

// ===================== host =================================================
extern "C" void kernel_launch(void* const* d_in, const int* in_sizes, int n_in,
                              void* d_out, int out_size)
{
    const float* x_in = (const float*)d_in[0];
    const float* wq = (const float*)d_in[1];
    const float* bq = (const float*)d_in[2];
    const float* wk = (const float*)d_in[3];
    const float* bk = (const float*)d_in[4];
    const float* wv = (const float*)d_in[5];
    const float* bv = (const float*)d_in[6];
    const float* wo = (const float*)d_in[7];
    const float* bo = (const float*)d_in[8];
    const float* w1 = (const float*)d_in[9];
    const float* b1 = (const float*)d_in[10];
    const float* w2 = (const float*)d_in[11];
    const float* b2 = (const float*)d_in[12];
    const float* ln1g = (const float*)d_in[13];
    const float* ln1b = (const float*)d_in[14];
    const float* ln2g = (const float*)d_in[15];
    const float* ln2b = (const float*)d_in[16];

    float *x, *t1, *bqkv;
    __half *xp, *cp, *hp, *wqkvp, *wop, *w1p, *w2p, *qkvb;
    cudaGetSymbolAddress((void**)&x,     g_x);
    cudaGetSymbolAddress((void**)&t1,    g_t1);
    cudaGetSymbolAddress((void**)&bqkv,  g_bqkv);
    cudaGetSymbolAddress((void**)&xp,    g_xp);
    cudaGetSymbolAddress((void**)&cp,    g_cp);
    cudaGetSymbolAddress((void**)&hp,    g_hp);
    cudaGetSymbolAddress((void**)&wqkvp, g_wqkvp);
    cudaGetSymbolAddress((void**)&wop,   g_wop);
    cudaGetSymbolAddress((void**)&w1p,   g_w1p);
    cudaGetSymbolAddress((void**)&w2p,   g_w2p);
    cudaGetSymbolAddress((void**)&qkvb,  g_qkvb);

    const int FLASH_SMEM = 5 * 128 * FSTR;
    cudaFuncSetAttribute(flash_attn,
        cudaFuncAttributeMaxDynamicSharedMemorySize, FLASH_SMEM);

    cudaMemcpyAsync(x, x_in, sizeof(float) * SEQ * D_MODEL,
                    cudaMemcpyDeviceToDevice, 0);

    const dim3 blk(256);

    // initial pack of x; later layers get xp from add_ln
    pack_x<<<dim3(D_MODEL/256, SEQ), blk>>>(x, xp, D_MODEL);

    for (int l = 0; l < NLAYERS; l++) {
        const float* Wq = wq + (size_t)l * D_MODEL * D_MODEL;
        const float* Wk = wk + (size_t)l * D_MODEL * D_MODEL;
        const float* Wv = wv + (size_t)l * D_MODEL * D_MODEL;
        const float* Wo = wo + (size_t)l * D_MODEL * D_MODEL;
        const float* W1 = w1 + (size_t)l * D_MODEL * DFF;
        const float* W2 = w2 + (size_t)l * DFF * D_MODEL;

        // ---- pack weights (single-segment fp16, transposed [N,K]) ----
        pack_wT<<<dim3(D_MODEL/32, D_MODEL/32), blk>>>(Wq, D_MODEL, wqkvp, D_MODEL);
        pack_wT<<<dim3(D_MODEL/32, D_MODEL/32), blk>>>(Wk, D_MODEL,
            wqkvp + (size_t)D_MODEL * D_MODEL, D_MODEL);
        pack_wT<<<dim3(D_MODEL/32, D_MODEL/32), blk>>>(Wv, D_MODEL,
            wqkvp + (size_t)2 * D_MODEL * D_MODEL, D_MODEL);
        pack_wT<<<dim3(D_MODEL/32, D_MODEL/32), blk>>>(Wo, D_MODEL, wop, D_MODEL);
        pack_wT<<<dim3(DFF/32,     D_MODEL/32), blk>>>(W1, DFF,     w1p, D_MODEL);
        pack_wT<<<dim3(D_MODEL/32, DFF/32),     blk>>>(W2, D_MODEL, w2p, DFF);
        concat_bias<<<dim3(3 * D_MODEL / 256), blk>>>(
            bq + (size_t)l * D_MODEL, bk + (size_t)l * D_MODEL,
            bv + (size_t)l * D_MODEL, bqkv);

        // ---- fused QKV projection (1-segment fp16) -> head-major fp16 ----
        gemm_tc<128, 4><<<dim3(3 * D_MODEL / 128, SEQ / 128), blk>>>(
            xp, 2 * D_MODEL, wqkvp, D_MODEL, (float*)qkvb, 0,
            bqkv, D_MODEL / 32, 1, 0, 1.0f);

        // ---- flash attention -> fp16 ctx ----
        flash_attn<<<dim3(SEQ / 128, NHEAD), blk, FLASH_SMEM>>>(qkvb, cp);

        // ---- output projection (1-segment) + LN1 (emits x + xp) ----
        gemm_tc<128, 0><<<dim3(D_MODEL / 128, SEQ / 128), blk>>>(
            cp, D_MODEL, wop, D_MODEL, t1, D_MODEL,
            bo + (size_t)l * D_MODEL, D_MODEL / 32, 1, 0, 1.0f);
        add_ln_kernel<<<SEQ, blk>>>(x, t1,
            ln1g + (size_t)l * D_MODEL, ln1b + (size_t)l * D_MODEL, xp);

        // ---- FFN (2-segment activations x single-segment weights) ----
        gemm_tc<128, 3><<<dim3(DFF / 128, SEQ / 128), blk>>>(
            xp, 2 * D_MODEL, w1p, D_MODEL, (float*)hp, DFF,
            b1 + (size_t)l * DFF, D_MODEL / 32, 2, D_MODEL, 1.0f);
        gemm_tc<128, 0><<<dim3(D_MODEL / 128, SEQ / 128), blk>>>(
            hp, 2 * DFF, w2p, DFF, t1, D_MODEL,
            b2 + (size_t)l * D_MODEL, DFF / 32, 2, DFF, 1.0f);
        add_ln_kernel<<<SEQ, blk>>>(x, t1,
            ln2g + (size_t)l * D_MODEL, ln2b + (size_t)l * D_MODEL, xp);
    }

    cudaMemcpyAsync(d_out, x, sizeof(float) * SEQ * D_MODEL,
                    cudaMemcpyDeviceToDevice, 0);
}